// round 7
// baseline (speedup 1.0000x reference)
#include <cuda_runtime.h>
#include <cstdint>
#include <math.h>

#define TT 256
#define BB 64
#define EE 256
#define HH 512
#define KK 32
#define G4H 2048
#define MROWS (TT*BB)          // 16384

// ---------------- scratch (static device allocations; no cudaMalloc) ------------
__device__ float    g_xpf[MROWS*G4H];        // input proj fwd      (T,B,4H)
__device__ float    g_xpr[MROWS*G4H];        // input proj rev      (T,B,4H)
__device__ float    g_hbuf[MROWS*2*HH];      // layer output        (T,B,2H)
__device__ float    g_feats[MROWS*KK];       // emissions           (T,B,K)
__device__ float    g_hsthi[2*2*BB*HH];      // [buf][dir][B][H] h hi split
__device__ float    g_hstlo[2*2*BB*HH];      // [buf][dir][B][H] h lo split
__device__ unsigned g_bar[2];                // per-direction barrier counters
// tf32 hi/lo splits (fp32 bit patterns, tf32-rounded)
__device__ __align__(16) float g_as[2][MROWS*EE];      // embedded x splits
__device__ __align__(16) float g_hs[2][MROWS*2*HH];    // hbuf splits (written by lstm L0)
__device__ __align__(16) float g_w0f[2][G4H*EE];
__device__ __align__(16) float g_w0r[2][G4H*EE];
__device__ __align__(16) float g_w1f[2][G4H*2*HH];
__device__ __align__(16) float g_w1r[2][G4H*2*HH];

// single dynamic-smem symbol shared by all kernels
extern __shared__ __align__(16) char dynsmem[];

// ---------------- small helpers --------------------------------------------------
__device__ __forceinline__ float sigm(float x) { return 1.0f / (1.0f + expf(-x)); }

__device__ __forceinline__ void split_tf32(float x, float& hi, float& lo) {
    uint32_t h;
    asm("cvt.rna.tf32.f32 %0, %1;" : "=r"(h) : "f"(x));
    hi = __uint_as_float(h);
    float r = x - hi;
    uint32_t l;
    asm("cvt.rna.tf32.f32 %0, %1;" : "=r"(l) : "f"(r));
    lo = __uint_as_float(l);
}

__device__ __forceinline__ uint32_t smem_u32(const void* p) {
    uint32_t a;
    asm("{ .reg .u64 t; cvta.to.shared.u64 t, %1; cvt.u32.u64 %0, t; }"
        : "=r"(a) : "l"(p));
    return a;
}
__device__ __forceinline__ void cp16(uint32_t dst, const void* src) {
    asm volatile("cp.async.cg.shared.global [%0], [%1], 16;"
                 :: "r"(dst), "l"(src) : "memory");
}
__device__ __forceinline__ void cp_commit() {
    asm volatile("cp.async.commit_group;" ::: "memory");
}
__device__ __forceinline__ void cp_wait1() {
    asm volatile("cp.async.wait_group 1;" ::: "memory");
}
__device__ __forceinline__ void cp_wait0() {
    asm volatile("cp.async.wait_group 0;" ::: "memory");
}
__device__ __forceinline__ void mma_tf32(float* d, const uint32_t* a,
                                         uint32_t b0, uint32_t b1) {
    asm volatile(
        "mma.sync.aligned.m16n8k8.row.col.f32.tf32.tf32.f32 "
        "{%0,%1,%2,%3}, {%4,%5,%6,%7}, {%8,%9}, {%0,%1,%2,%3};"
        : "+f"(d[0]), "+f"(d[1]), "+f"(d[2]), "+f"(d[3])
        : "r"(a[0]), "r"(a[1]), "r"(a[2]), "r"(a[3]), "r"(b0), "r"(b1));
}

// ---------------- tf32 split of an fp32 array (float4 granularity) --------------
__global__ void split2_kernel(const float* __restrict__ in, float* __restrict__ oh,
                              float* __restrict__ ol, int n4) {
    int i = blockIdx.x * blockDim.x + threadIdx.x;
    if (i >= n4) return;
    float4 a = reinterpret_cast<const float4*>(in)[i];
    float4 h, l;
    split_tf32(a.x, h.x, l.x);
    split_tf32(a.y, h.y, l.y);
    split_tf32(a.z, h.z, l.z);
    split_tf32(a.w, h.w, l.w);
    reinterpret_cast<float4*>(oh)[i] = h;
    reinterpret_cast<float4*>(ol)[i] = l;
}

// ---------------- embedding gather fused with tf32 split ------------------------
__global__ void embed_split_kernel(const int* __restrict__ sent,
                                   const float* __restrict__ emb,
                                   float* __restrict__ oh, float* __restrict__ ol) {
    int i = blockIdx.x * blockDim.x + threadIdx.x;      // over T*B*(E/4)
    int total = TT * BB * (EE / 4);
    if (i >= total) return;
    int tb = i >> 6;
    int e4 = i & 63;
    int v = sent[tb];
    float4 a = reinterpret_cast<const float4*>(emb + (size_t)v * EE)[e4];
    float4 h, l;
    split_tf32(a.x, h.x, l.x);
    split_tf32(a.y, h.y, l.y);
    split_tf32(a.z, h.z, l.z);
    split_tf32(a.w, h.w, l.w);
    reinterpret_cast<float4*>(oh)[i] = h;
    reinterpret_cast<float4*>(ol)[i] = l;
}

// ---------------- 3xTF32 mma.sync GEMM (validated round 4) ----------------------
#define TPAD 20
#define TILE_F (128 * TPAD)
#define STAGE_F (4 * TILE_F)
#define GEMM_SMEM (2 * STAGE_F * 4)

__global__ __launch_bounds__(256) void tf32_gemm(
    const float* __restrict__ Ah, const float* __restrict__ Al,
    const float* __restrict__ Wh, const float* __restrict__ Wl,
    const float* __restrict__ bi1, const float* __restrict__ bi2,
    float* __restrict__ C, int K)
{
    float* smem = reinterpret_cast<float*>(dynsmem);
    const uint32_t sb = smem_u32(smem);
    const int tid = threadIdx.x, lane = tid & 31, wid = tid >> 5;
    const int wm = wid & 1, wn = wid >> 1;
    const int bn = blockIdx.x * 128, bm = blockIdx.y * 128;
    const int nch = K >> 4;
    const int qr = lane >> 2, qc = lane & 3;

    float acc[4][4][4];
    #pragma unroll
    for (int mi = 0; mi < 4; mi++)
        #pragma unroll
        for (int ni = 0; ni < 4; ni++)
            #pragma unroll
            for (int q = 0; q < 4; q++) acc[mi][ni][q] = 0.0f;

    auto issue = [&](int c, int st) {
        #pragma unroll
        for (int i = 0; i < 8; i++) {
            int s = tid + i * 256;
            int tile = s >> 9;
            int r = (s >> 2) & 127;
            int sub = s & 3;
            const float* g;
            if (tile == 0)      g = Ah + (size_t)(bm + r) * K + c * 16 + sub * 4;
            else if (tile == 1) g = Al + (size_t)(bm + r) * K + c * 16 + sub * 4;
            else if (tile == 2) g = Wh + (size_t)(bn + r) * K + c * 16 + sub * 4;
            else                g = Wl + (size_t)(bn + r) * K + c * 16 + sub * 4;
            uint32_t d = sb + (uint32_t)(st * STAGE_F + tile * TILE_F + r * TPAD + sub * 4) * 4;
            cp16(d, g);
        }
        cp_commit();
    };

    issue(0, 0);

    for (int c = 0; c < nch; c++) {
        const int st = c & 1;
        if (c + 1 < nch) { issue(c + 1, st ^ 1); cp_wait1(); }
        else cp_wait0();
        __syncthreads();

        const float* Ah_s = smem + st * STAGE_F;
        const float* Al_s = Ah_s + TILE_F;
        const float* Wh_s = Ah_s + 2 * TILE_F;
        const float* Wl_s = Ah_s + 3 * TILE_F;

        #pragma unroll
        for (int s8 = 0; s8 < 16; s8 += 8) {
            #pragma unroll
            for (int t = 0; t < 3; t++) {
                const float* At = (t == 2) ? Al_s : Ah_s;
                const float* Wt = (t == 1) ? Wl_s : Wh_s;
                uint32_t a[4][4];
                #pragma unroll
                for (int mi = 0; mi < 4; mi++) {
                    int m = wm * 64 + mi * 16 + qr;
                    const uint32_t* p =
                        reinterpret_cast<const uint32_t*>(At + m * TPAD + s8 + qc);
                    a[mi][0] = p[0];
                    a[mi][2] = p[4];
                    const uint32_t* p8 =
                        reinterpret_cast<const uint32_t*>(At + (m + 8) * TPAD + s8 + qc);
                    a[mi][1] = p8[0];
                    a[mi][3] = p8[4];
                }
                #pragma unroll
                for (int ni = 0; ni < 4; ni++) {
                    int n = wn * 32 + ni * 8 + qr;
                    const uint32_t* p =
                        reinterpret_cast<const uint32_t*>(Wt + n * TPAD + s8 + qc);
                    uint32_t b0 = p[0], b1 = p[4];
                    #pragma unroll
                    for (int mi = 0; mi < 4; mi++)
                        mma_tf32(acc[mi][ni], a[mi], b0, b1);
                }
            }
        }
        __syncthreads();
    }

    #pragma unroll
    for (int ni = 0; ni < 4; ni++) {
        int col = bn + wn * 32 + ni * 8 + 2 * qc;
        float2 s1 = *reinterpret_cast<const float2*>(bi1 + col);
        float2 s2 = *reinterpret_cast<const float2*>(bi2 + col);
        float bx = s1.x + s2.x, by = s1.y + s2.y;
        #pragma unroll
        for (int mi = 0; mi < 4; mi++) {
            int row = bm + wm * 64 + mi * 16 + qr;
            float2 v0 = make_float2(acc[mi][ni][0] + bx, acc[mi][ni][1] + by);
            float2 v1 = make_float2(acc[mi][ni][2] + bx, acc[mi][ni][3] + by);
            *reinterpret_cast<float2*>(&C[(size_t)row * G4H + col]) = v0;
            *reinterpret_cast<float2*>(&C[(size_t)(row + 8) * G4H + col]) = v1;
        }
    }
}

// ---------------- persistent LSTM layer, recurrent GEMM on tensor cores ---------
// 128 blocks (64/dir), 256 thr. Block owns 8 j-cols -> 32 W_hh rows (4 gates x 8 j).
// W_hh tf32-split in-kernel, resident in smem. h_prev hi/lo in global (L2-hot),
// cp.async-streamed in k=64 chunks, double buffered. 8 warps: 4 m-tiles x 2 n-halves,
// m16n8k8 x 3 tf32 terms. C staged through smem; cell update + tf32 re-split of h.
#define WP  516                      // W smem row stride (floats), conflict-free
#define HP  68                       // h chunk row stride (floats)
#define OFF_WLO (32*WP*4)            // 66048
#define OFF_H   (2*32*WP*4)          // 132096
#define HBUFB   (64*HP*4)            // 17408 bytes per (buf,term)
#define OFF_CS  (OFF_H + 4*HBUFB)    // 201728
#define LSTM2_SMEM (OFF_CS + 64*34*4)  // 210432 bytes

__global__ __launch_bounds__(256) void lstm_mma_kernel(
    const float* __restrict__ xpf, const float* __restrict__ xpr,
    const float* __restrict__ whf, const float* __restrict__ whr,
    float* __restrict__ hout, float* hsthi, float* hstlo,
    float* __restrict__ hb_hi, float* __restrict__ hb_lo,
    unsigned* bar, int dosplit)
{
    char* smem = dynsmem;
    float* Whi = reinterpret_cast<float*>(smem);
    float* Wlo = reinterpret_cast<float*>(smem + OFF_WLO);
    float* Cs  = reinterpret_cast<float*>(smem + OFF_CS);
    const uint32_t sb = smem_u32(smem);
    const int tid = threadIdx.x, lane = tid & 31, wid = tid >> 5;
    const int dir = blockIdx.x >> 6, sub = blockIdx.x & 63, j0 = sub * 8;
    const float* W  = dir ? whr : whf;
    const float* xp = dir ? xpr : xpf;
    const int qr = lane >> 2, qc = lane & 3;
    const int m0 = (wid & 3) * 16, nh = wid >> 2;

    // load + tf32-split W_hh slice (rows gate*512 + j0 + jl), row r = gate*8 + jl
    for (int i = tid; i < 32 * 512; i += 256) {
        int r = i >> 9, c = i & 511;
        int gate = r >> 3, jj = r & 7;
        float v = W[(size_t)(gate * 512 + j0 + jj) * HH + c];
        float hi, lo;
        split_tf32(v, hi, lo);
        Whi[r * WP + c] = hi;
        Wlo[r * WP + c] = lo;
    }
    __syncthreads();

    const int jl = tid & 7, b0 = tid >> 3, b1 = b0 + 32;
    const int j = j0 + jl;
    float c0 = 0.0f, c1 = 0.0f;

    for (int s = 0; s < TT; s++) {
        const int rb = s & 1, wb = rb ^ 1;
        const int tt = dir ? (TT - 1 - s) : s;
        const float* xpt = xp + (size_t)tt * BB * G4H;

        // prefetch input-projection gate values (DRAM)
        float xg[8];
        #pragma unroll
        for (int g = 0; g < 4; g++) {
            xg[g]     = xpt[b0 * G4H + g * HH + j];
            xg[g + 4] = xpt[b1 * G4H + g * HH + j];
        }

        const float* ghi = hsthi + (size_t)(rb * 2 + dir) * (BB * HH);
        const float* glo = hstlo + (size_t)(rb * 2 + dir) * (BB * HH);

        auto issue = [&](int c, int st) {
            uint32_t base = sb + OFF_H + (uint32_t)st * 2 * HBUFB;
            #pragma unroll
            for (int i = 0; i < 4; i++) {
                int sg = tid + i * 256;          // 1024 16B segments per term
                int row = sg >> 4, seg = sg & 15;
                uint32_t off = (uint32_t)(row * HP + seg * 4) * 4;
                const float* srch = ghi + (size_t)row * HH + c * 64 + seg * 4;
                const float* srcl = glo + (size_t)row * HH + c * 64 + seg * 4;
                cp16(base + off, srch);
                cp16(base + HBUFB + off, srcl);
            }
            cp_commit();
        };

        float acc[2][4] = {{0.f,0.f,0.f,0.f},{0.f,0.f,0.f,0.f}};
        issue(0, 0);
        for (int ch = 0; ch < 8; ch++) {
            const int st = ch & 1;
            if (ch < 7) { issue(ch + 1, st ^ 1); cp_wait1(); }
            else cp_wait0();
            __syncthreads();

            const uint32_t* Hh =
                reinterpret_cast<const uint32_t*>(smem + OFF_H + st * 2 * HBUFB);
            const uint32_t* Hl = Hh + 64 * HP;
            const uint32_t* Whu = reinterpret_cast<const uint32_t*>(Whi);
            const uint32_t* Wlu = reinterpret_cast<const uint32_t*>(Wlo);

            #pragma unroll
            for (int ko = 0; ko < 8; ko++) {
                const int c = ko * 8 + qc;
                uint32_t ah[4], al[4];
                ah[0] = Hh[(m0 + qr) * HP + c];
                ah[1] = Hh[(m0 + qr + 8) * HP + c];
                ah[2] = Hh[(m0 + qr) * HP + c + 4];
                ah[3] = Hh[(m0 + qr + 8) * HP + c + 4];
                al[0] = Hl[(m0 + qr) * HP + c];
                al[1] = Hl[(m0 + qr + 8) * HP + c];
                al[2] = Hl[(m0 + qr) * HP + c + 4];
                al[3] = Hl[(m0 + qr + 8) * HP + c + 4];
                const int kg = ch * 64 + ko * 8 + qc;
                #pragma unroll
                for (int nt = 0; nt < 2; nt++) {
                    const int n = nh * 16 + nt * 8 + qr;
                    uint32_t bh0 = Whu[n * WP + kg], bh1 = Whu[n * WP + kg + 4];
                    uint32_t bl0 = Wlu[n * WP + kg], bl1 = Wlu[n * WP + kg + 4];
                    mma_tf32(acc[nt], ah, bh0, bh1);
                    mma_tf32(acc[nt], al, bh0, bh1);
                    mma_tf32(acc[nt], ah, bl0, bl1);
                }
            }
            __syncthreads();
        }

        // stage C fragments -> smem (row b, col = gate*8 + jl)
        #pragma unroll
        for (int nt = 0; nt < 2; nt++) {
            int ncol = nh * 16 + nt * 8 + 2 * qc;
            *reinterpret_cast<float2*>(&Cs[(m0 + qr) * 34 + ncol]) =
                make_float2(acc[nt][0], acc[nt][1]);
            *reinterpret_cast<float2*>(&Cs[(m0 + qr + 8) * 34 + ncol]) =
                make_float2(acc[nt][2], acc[nt][3]);
        }
        __syncthreads();

        // cell update: thread owns (j = j0+jl, batches b0 and b0+32)
        float gi0 = Cs[b0 * 34 + 0 * 8 + jl] + xg[0];
        float gf0 = Cs[b0 * 34 + 1 * 8 + jl] + xg[1];
        float gg0 = Cs[b0 * 34 + 2 * 8 + jl] + xg[2];
        float go0 = Cs[b0 * 34 + 3 * 8 + jl] + xg[3];
        float gi1 = Cs[b1 * 34 + 0 * 8 + jl] + xg[4];
        float gf1 = Cs[b1 * 34 + 1 * 8 + jl] + xg[5];
        float gg1 = Cs[b1 * 34 + 2 * 8 + jl] + xg[6];
        float go1 = Cs[b1 * 34 + 3 * 8 + jl] + xg[7];

        c0 = sigm(gf0) * c0 + sigm(gi0) * tanhf(gg0);
        float h0v = sigm(go0) * tanhf(c0);
        c1 = sigm(gf1) * c1 + sigm(gi1) * tanhf(gg1);
        float h1v = sigm(go1) * tanhf(c1);

        float* dhi = hsthi + (size_t)(wb * 2 + dir) * (BB * HH);
        float* dlo = hstlo + (size_t)(wb * 2 + dir) * (BB * HH);
        float h0h, h0l, h1h, h1l;
        split_tf32(h0v, h0h, h0l);
        split_tf32(h1v, h1h, h1l);
        dhi[b0 * HH + j] = h0h; dlo[b0 * HH + j] = h0l;
        dhi[b1 * HH + j] = h1h; dlo[b1 * HH + j] = h1l;

        size_t o0 = (size_t)(tt * BB + b0) * (2 * HH) + dir * HH + j;
        size_t o1 = (size_t)(tt * BB + b1) * (2 * HH) + dir * HH + j;
        hout[o0] = h0v;
        hout[o1] = h1v;
        if (dosplit) {
            hb_hi[o0] = h0h; hb_lo[o0] = h0l;
            hb_hi[o1] = h1h; hb_lo[o1] = h1l;
        }

        __threadfence();
        __syncthreads();
        if (s + 1 < TT) {
            if (tid == 0) {
                atomicAdd(&bar[dir], 1u);
                unsigned target = 64u * (unsigned)(s + 1);
                volatile unsigned* p = bar + dir;
                while (*p < target) __nanosleep(64);
                __threadfence();
            }
            __syncthreads();
        }
    }
}

// ---------------- emissions: feats = hbuf @ W_out^T + b_out ---------------------
__global__ __launch_bounds__(128) void feats_kernel(
    const float* __restrict__ h, const float* __restrict__ Wout,
    const float* __restrict__ bout, float* __restrict__ feats)
{
    __shared__ __align__(16) float hs[4][2 * HH];
    int m0 = blockIdx.x * 4;
    int tid = threadIdx.x;
    for (int i = tid * 4; i < 4 * 2 * HH; i += 128 * 4)
        *reinterpret_cast<float4*>(&hs[0][i]) =
            *reinterpret_cast<const float4*>(&h[(size_t)m0 * 2 * HH + i]);
    __syncthreads();
    int r = tid >> 5, tag = tid & 31;
    const float* w = Wout + (size_t)tag * (2 * HH);
    float acc = 0.0f;
    #pragma unroll 4
    for (int k = 0; k < 2 * HH; k += 4) {
        float4 wv = *reinterpret_cast<const float4*>(&w[k]);
        float4 hv = *reinterpret_cast<const float4*>(&hs[r][k]);
        acc += wv.x * hv.x + wv.y * hv.y + wv.z * hv.z + wv.w * hv.w;
    }
    feats[(size_t)(m0 + r) * KK + tag] = acc + bout[tag];
}

// ---------------- Viterbi: one block (32 threads) per batch row -----------------
__global__ __launch_bounds__(32) void viterbi_kernel(
    const float* __restrict__ feats, const float* __restrict__ trans,
    const float* __restrict__ startt, const float* __restrict__ stopt,
    float* __restrict__ out, int out_size)
{
    int b = blockIdx.x;
    int j = threadIdx.x;
    __shared__ unsigned char bp[TT - 1][KK];
    __shared__ int path[TT];

    float tr[KK];
    #pragma unroll
    for (int k = 0; k < KK; k++) tr[k] = trans[j * KK + k];

    float dp = startt[j] + feats[(size_t)b * KK + j];
    for (int t = 1; t < TT; t++) {
        float best = -INFINITY;
        int arg = 0;
        #pragma unroll
        for (int k = 0; k < KK; k++) {
            float v = tr[k] + __shfl_sync(0xffffffffu, dp, k);
            if (v > best) { best = v; arg = k; }
        }
        bp[t - 1][j] = (unsigned char)arg;
        dp = best + feats[((size_t)t * BB + b) * KK + j];
    }
    dp += stopt[j];

    float bv = dp; int bi = j;
    #pragma unroll
    for (int off = 16; off; off >>= 1) {
        float ov = __shfl_down_sync(0xffffffffu, bv, off);
        int   oi = __shfl_down_sync(0xffffffffu, bi, off);
        if (ov > bv || (ov == bv && oi < bi)) { bv = ov; bi = oi; }
    }
    bv = __shfl_sync(0xffffffffu, bv, 0);
    bi = __shfl_sync(0xffffffffu, bi, 0);

    if (j == 0) {
        path[TT - 1] = bi;
        int tag = bi;
        for (int t = TT - 2; t >= 0; t--) {
            tag = bp[t][tag];
            path[t] = tag;
        }
    }
    __syncwarp();

    int pathsOff = out_size - TT * BB;
    if (pathsOff >= (int)BB) {
        if (j == 0) out[b] = bv;
    } else if (pathsOff < 0) {
        if (j == 0 && b < out_size) out[b] = bv;
        return;
    }
    for (int t = j; t < TT; t += 32)
        out[pathsOff + t * BB + b] = (float)path[t];
}

// ---------------- launch ---------------------------------------------------------
extern "C" void kernel_launch(void* const* d_in, const int* in_sizes, int n_in,
                              void* d_out, int out_size) {
    const int*   sent    = (const int*)d_in[0];
    const float* emb     = (const float*)d_in[1];
    const float* wih_l0f = (const float*)d_in[2];
    const float* whh_l0f = (const float*)d_in[3];
    const float* bih_l0f = (const float*)d_in[4];
    const float* bhh_l0f = (const float*)d_in[5];
    const float* wih_l0r = (const float*)d_in[6];
    const float* whh_l0r = (const float*)d_in[7];
    const float* bih_l0r = (const float*)d_in[8];
    const float* bhh_l0r = (const float*)d_in[9];
    const float* wih_l1f = (const float*)d_in[10];
    const float* whh_l1f = (const float*)d_in[11];
    const float* bih_l1f = (const float*)d_in[12];
    const float* bhh_l1f = (const float*)d_in[13];
    const float* wih_l1r = (const float*)d_in[14];
    const float* whh_l1r = (const float*)d_in[15];
    const float* bih_l1r = (const float*)d_in[16];
    const float* bhh_l1r = (const float*)d_in[17];
    const float* W_out   = (const float*)d_in[18];
    const float* b_out   = (const float*)d_in[19];
    const float* transit = (const float*)d_in[20];
    const float* start_t = (const float*)d_in[21];
    const float* stop_t  = (const float*)d_in[22];

    float *xpf, *xpr, *hbuf, *feats, *hsthi, *hstlo;
    unsigned* bar;
    cudaGetSymbolAddress((void**)&xpf,   g_xpf);
    cudaGetSymbolAddress((void**)&xpr,   g_xpr);
    cudaGetSymbolAddress((void**)&hbuf,  g_hbuf);
    cudaGetSymbolAddress((void**)&feats, g_feats);
    cudaGetSymbolAddress((void**)&hsthi, g_hsthi);
    cudaGetSymbolAddress((void**)&hstlo, g_hstlo);
    cudaGetSymbolAddress((void**)&bar,   g_bar);
    float *as, *hsx, *w0f, *w0r, *w1f, *w1r;
    cudaGetSymbolAddress((void**)&as,  g_as);
    cudaGetSymbolAddress((void**)&hsx, g_hs);
    cudaGetSymbolAddress((void**)&w0f, g_w0f);
    cudaGetSymbolAddress((void**)&w0r, g_w0r);
    cudaGetSymbolAddress((void**)&w1f, g_w1f);
    cudaGetSymbolAddress((void**)&w1r, g_w1r);
    const size_t ASZ = (size_t)MROWS*EE, HSZ = (size_t)MROWS*2*HH;
    const size_t W0SZ = (size_t)G4H*EE,  W1SZ = (size_t)G4H*2*HH;

    cudaFuncSetAttribute(tf32_gemm,
                         cudaFuncAttributeMaxDynamicSharedMemorySize, GEMM_SMEM);
    cudaFuncSetAttribute(lstm_mma_kernel,
                         cudaFuncAttributeMaxDynamicSharedMemorySize, LSTM2_SMEM);

    // 1) embedding (fused gather + tf32 split)
    embed_split_kernel<<<(TT * BB * (EE / 4) + 255) / 256, 256>>>(
        sent, emb, as, as + ASZ);

    // 2) split input-projection weights (all independent of the pipeline)
    split2_kernel<<<(int)(W0SZ/4 + 255)/256, 256>>>(wih_l0f, w0f, w0f + W0SZ, (int)(W0SZ/4));
    split2_kernel<<<(int)(W0SZ/4 + 255)/256, 256>>>(wih_l0r, w0r, w0r + W0SZ, (int)(W0SZ/4));
    split2_kernel<<<(int)(W1SZ/4 + 255)/256, 256>>>(wih_l1f, w1f, w1f + W1SZ, (int)(W1SZ/4));
    split2_kernel<<<(int)(W1SZ/4 + 255)/256, 256>>>(wih_l1r, w1r, w1r + W1SZ, (int)(W1SZ/4));

    dim3 gg(G4H / 128, MROWS / 128);   // (16, 128)

    // 3) layer-0 input projections (tensor cores, 3xTF32)
    tf32_gemm<<<gg, 256, GEMM_SMEM>>>(as, as + ASZ, w0f, w0f + W0SZ,
                                      bih_l0f, bhh_l0f, xpf, EE);
    tf32_gemm<<<gg, 256, GEMM_SMEM>>>(as, as + ASZ, w0r, w0r + W0SZ,
                                      bih_l0r, bhh_l0r, xpr, EE);

    // 4) layer-0 recurrence (tensor cores); writes hbuf + its tf32 splits
    cudaMemsetAsync(hsthi, 0, sizeof(float) * 2 * 2 * BB * HH);
    cudaMemsetAsync(hstlo, 0, sizeof(float) * 2 * 2 * BB * HH);
    cudaMemsetAsync(bar, 0, sizeof(unsigned) * 2);
    lstm_mma_kernel<<<128, 256, LSTM2_SMEM>>>(xpf, xpr, whh_l0f, whh_l0r,
                                              hbuf, hsthi, hstlo,
                                              hsx, hsx + HSZ, bar, 1);

    // 5) layer-1 input projections (K = 2H), A = hbuf splits from step 4
    tf32_gemm<<<gg, 256, GEMM_SMEM>>>(hsx, hsx + HSZ, w1f, w1f + W1SZ,
                                      bih_l1f, bhh_l1f, xpf, 2 * HH);
    tf32_gemm<<<gg, 256, GEMM_SMEM>>>(hsx, hsx + HSZ, w1r, w1r + W1SZ,
                                      bih_l1r, bhh_l1r, xpr, 2 * HH);

    // 6) layer-1 recurrence (overwrites hbuf; no splits needed)
    cudaMemsetAsync(hsthi, 0, sizeof(float) * 2 * 2 * BB * HH);
    cudaMemsetAsync(hstlo, 0, sizeof(float) * 2 * 2 * BB * HH);
    cudaMemsetAsync(bar, 0, sizeof(unsigned) * 2);
    lstm_mma_kernel<<<128, 256, LSTM2_SMEM>>>(xpf, xpr, whh_l1f, whh_l1r,
                                              hbuf, hsthi, hstlo,
                                              hsx, hsx + HSZ, bar, 0);

    // 7) emissions
    feats_kernel<<<MROWS / 4, 128>>>(hbuf, W_out, b_out, feats);

    // 8) Viterbi decode + output write
    viterbi_kernel<<<BB, 32>>>(feats, transit, start_t, stop_t, (float*)d_out, out_size);
}

// round 8
// speedup vs baseline: 1.0960x; 1.0960x over previous
#include <cuda_runtime.h>
#include <cstdint>
#include <math.h>

#define TT 256
#define BB 64
#define EE 256
#define HH 512
#define KK 32
#define G4H 2048
#define MROWS (TT*BB)

// ---------------- scratch (static device allocations) ---------------------------
__device__ float    g_xpf[MROWS*G4H];
__device__ float    g_xpr[MROWS*G4H];
__device__ float    g_hbuf[MROWS*2*HH];
__device__ float    g_feats[MROWS*KK];
__device__ float    g_hst2[2*2*BB*1024];     // [buf][dir][B][j*2] interleaved hi/lo
__device__ unsigned g_bar[2];
__device__ __align__(16) float g_as[2][MROWS*EE];
__device__ __align__(16) float g_hs[2][MROWS*2*HH];
__device__ __align__(16) float g_w0f[2][G4H*EE];
__device__ __align__(16) float g_w0r[2][G4H*EE];
__device__ __align__(16) float g_w1f[2][G4H*2*HH];
__device__ __align__(16) float g_w1r[2][G4H*2*HH];

extern __shared__ __align__(16) char dynsmem[];

// ---------------- helpers --------------------------------------------------------
__device__ __forceinline__ float sigm(float x) { return 1.0f / (1.0f + expf(-x)); }

__device__ __forceinline__ void split_tf32(float x, float& hi, float& lo) {
    uint32_t h;
    asm("cvt.rna.tf32.f32 %0, %1;" : "=r"(h) : "f"(x));
    hi = __uint_as_float(h);
    float r = x - hi;
    uint32_t l;
    asm("cvt.rna.tf32.f32 %0, %1;" : "=r"(l) : "f"(r));
    lo = __uint_as_float(l);
}
__device__ __forceinline__ uint32_t smem_u32(const void* p) {
    uint32_t a;
    asm("{ .reg .u64 t; cvta.to.shared.u64 t, %1; cvt.u32.u64 %0, t; }"
        : "=r"(a) : "l"(p));
    return a;
}
__device__ __forceinline__ void cp16(uint32_t dst, const void* src) {
    asm volatile("cp.async.cg.shared.global [%0], [%1], 16;"
                 :: "r"(dst), "l"(src) : "memory");
}
__device__ __forceinline__ void cp_commit() {
    asm volatile("cp.async.commit_group;" ::: "memory");
}
__device__ __forceinline__ void cp_wait1() {
    asm volatile("cp.async.wait_group 1;" ::: "memory");
}
__device__ __forceinline__ void cp_wait0() {
    asm volatile("cp.async.wait_group 0;" ::: "memory");
}
__device__ __forceinline__ void mma_tf32(float* d, const uint32_t* a,
                                         uint32_t b0, uint32_t b1) {
    asm volatile(
        "mma.sync.aligned.m16n8k8.row.col.f32.tf32.tf32.f32 "
        "{%0,%1,%2,%3}, {%4,%5,%6,%7}, {%8,%9}, {%0,%1,%2,%3};"
        : "+f"(d[0]), "+f"(d[1]), "+f"(d[2]), "+f"(d[3])
        : "r"(a[0]), "r"(a[1]), "r"(a[2]), "r"(a[3]), "r"(b0), "r"(b1));
}

// ---------------- tf32 split kernels ---------------------------------------------
__global__ void split2_kernel(const float* __restrict__ in, float* __restrict__ oh,
                              float* __restrict__ ol, int n4) {
    int i = blockIdx.x * blockDim.x + threadIdx.x;
    if (i >= n4) return;
    float4 a = reinterpret_cast<const float4*>(in)[i];
    float4 h, l;
    split_tf32(a.x, h.x, l.x);
    split_tf32(a.y, h.y, l.y);
    split_tf32(a.z, h.z, l.z);
    split_tf32(a.w, h.w, l.w);
    reinterpret_cast<float4*>(oh)[i] = h;
    reinterpret_cast<float4*>(ol)[i] = l;
}

__global__ void embed_split_kernel(const int* __restrict__ sent,
                                   const float* __restrict__ emb,
                                   float* __restrict__ oh, float* __restrict__ ol) {
    int i = blockIdx.x * blockDim.x + threadIdx.x;
    int total = TT * BB * (EE / 4);
    if (i >= total) return;
    int tb = i >> 6, e4 = i & 63;
    int v = sent[tb];
    float4 a = reinterpret_cast<const float4*>(emb + (size_t)v * EE)[e4];
    float4 h, l;
    split_tf32(a.x, h.x, l.x);
    split_tf32(a.y, h.y, l.y);
    split_tf32(a.z, h.z, l.z);
    split_tf32(a.w, h.w, l.w);
    reinterpret_cast<float4*>(oh)[i] = h;
    reinterpret_cast<float4*>(ol)[i] = l;
}

// ---------------- 3xTF32 mma.sync GEMM (validated round 4) ----------------------
#define TPAD 20
#define TILE_F (128 * TPAD)
#define STAGE_F (4 * TILE_F)
#define GEMM_SMEM (2 * STAGE_F * 4)

__global__ __launch_bounds__(256) void tf32_gemm(
    const float* __restrict__ Ah, const float* __restrict__ Al,
    const float* __restrict__ Wh, const float* __restrict__ Wl,
    const float* __restrict__ bi1, const float* __restrict__ bi2,
    float* __restrict__ C, int K)
{
    float* smem = reinterpret_cast<float*>(dynsmem);
    const uint32_t sb = smem_u32(smem);
    const int tid = threadIdx.x, lane = tid & 31, wid = tid >> 5;
    const int wm = wid & 1, wn = wid >> 1;
    const int bn = blockIdx.x * 128, bm = blockIdx.y * 128;
    const int nch = K >> 4;
    const int qr = lane >> 2, qc = lane & 3;

    float acc[4][4][4];
    #pragma unroll
    for (int mi = 0; mi < 4; mi++)
        #pragma unroll
        for (int ni = 0; ni < 4; ni++)
            #pragma unroll
            for (int q = 0; q < 4; q++) acc[mi][ni][q] = 0.0f;

    auto issue = [&](int c, int st) {
        #pragma unroll
        for (int i = 0; i < 8; i++) {
            int s = tid + i * 256;
            int tile = s >> 9;
            int r = (s >> 2) & 127;
            int sub = s & 3;
            const float* g;
            if (tile == 0)      g = Ah + (size_t)(bm + r) * K + c * 16 + sub * 4;
            else if (tile == 1) g = Al + (size_t)(bm + r) * K + c * 16 + sub * 4;
            else if (tile == 2) g = Wh + (size_t)(bn + r) * K + c * 16 + sub * 4;
            else                g = Wl + (size_t)(bn + r) * K + c * 16 + sub * 4;
            uint32_t d = sb + (uint32_t)(st * STAGE_F + tile * TILE_F + r * TPAD + sub * 4) * 4;
            cp16(d, g);
        }
        cp_commit();
    };

    issue(0, 0);

    for (int c = 0; c < nch; c++) {
        const int st = c & 1;
        if (c + 1 < nch) { issue(c + 1, st ^ 1); cp_wait1(); }
        else cp_wait0();
        __syncthreads();

        const float* Ah_s = smem + st * STAGE_F;
        const float* Al_s = Ah_s + TILE_F;
        const float* Wh_s = Ah_s + 2 * TILE_F;
        const float* Wl_s = Ah_s + 3 * TILE_F;

        #pragma unroll
        for (int s8 = 0; s8 < 16; s8 += 8) {
            #pragma unroll
            for (int t = 0; t < 3; t++) {
                const float* At = (t == 2) ? Al_s : Ah_s;
                const float* Wt = (t == 1) ? Wl_s : Wh_s;
                uint32_t a[4][4];
                #pragma unroll
                for (int mi = 0; mi < 4; mi++) {
                    int m = wm * 64 + mi * 16 + qr;
                    const uint32_t* p =
                        reinterpret_cast<const uint32_t*>(At + m * TPAD + s8 + qc);
                    a[mi][0] = p[0];
                    a[mi][2] = p[4];
                    const uint32_t* p8 =
                        reinterpret_cast<const uint32_t*>(At + (m + 8) * TPAD + s8 + qc);
                    a[mi][1] = p8[0];
                    a[mi][3] = p8[4];
                }
                #pragma unroll
                for (int ni = 0; ni < 4; ni++) {
                    int n = wn * 32 + ni * 8 + qr;
                    const uint32_t* p =
                        reinterpret_cast<const uint32_t*>(Wt + n * TPAD + s8 + qc);
                    uint32_t b0 = p[0], b1 = p[4];
                    #pragma unroll
                    for (int mi = 0; mi < 4; mi++)
                        mma_tf32(acc[mi][ni], a[mi], b0, b1);
                }
            }
        }
        __syncthreads();
    }

    #pragma unroll
    for (int ni = 0; ni < 4; ni++) {
        int col = bn + wn * 32 + ni * 8 + 2 * qc;
        float2 s1 = *reinterpret_cast<const float2*>(bi1 + col);
        float2 s2 = *reinterpret_cast<const float2*>(bi2 + col);
        float bx = s1.x + s2.x, by = s1.y + s2.y;
        #pragma unroll
        for (int mi = 0; mi < 4; mi++) {
            int row = bm + wm * 64 + mi * 16 + qr;
            float2 v0 = make_float2(acc[mi][ni][0] + bx, acc[mi][ni][1] + by);
            float2 v1 = make_float2(acc[mi][ni][2] + bx, acc[mi][ni][3] + by);
            *reinterpret_cast<float2*>(&C[(size_t)row * G4H + col]) = v0;
            *reinterpret_cast<float2*>(&C[(size_t)(row + 8) * G4H + col]) = v1;
        }
    }
}

// ---------------- persistent LSTM v3: k-split warps, register-resident W --------
// 128 blocks = dir(2) x 64 j-groups, 256 threads. Block tile: 32 gate rows x 64
// batch, K=512. Warp w owns K-slice [64w,64w+64); W_hh tf32 hi/lo frags in regs.
// h (interleaved hi/lo) streams via cp.async in 4 batch-chunks of 16, double
// buffered; each h element read from smem once. k-partials reduced via smem.
#define HROW 1032
#define HSTG (16 * HROW * 4)               // 66048 B per stage
#define OFF_PS (2 * HSTG)                  // 132096
#define OFF_GS (OFF_PS + 8 * 640 * 4)      // 152576
#define LSTM3_SMEM (OFF_GS + 32 * 20 * 4)  // 155136 B

__global__ __launch_bounds__(256, 1) void lstm_mma2_kernel(
    const float* __restrict__ xpf, const float* __restrict__ xpr,
    const float* __restrict__ whf, const float* __restrict__ whr,
    float* __restrict__ hout, float* hst,
    float* __restrict__ hb_hi, float* __restrict__ hb_lo,
    unsigned* bar, int dosplit)
{
    float* Hs = reinterpret_cast<float*>(dynsmem);
    float* Ps = reinterpret_cast<float*>(dynsmem + OFF_PS);
    float* Gs = reinterpret_cast<float*>(dynsmem + OFF_GS);
    const uint32_t sb = smem_u32(dynsmem);
    const int tid = threadIdx.x, lane = tid & 31, wid = tid >> 5;
    const int dir = blockIdx.x >> 6, sub = blockIdx.x & 63, j0 = sub * 8;
    const float* W  = dir ? whr : whf;
    const float* xp = dir ? xpr : xpf;
    const int qr = lane >> 2, qc = lane & 3;
    const int k0 = wid * 64;

    // gather W_hh fragments (hi & lo) into registers — once per layer
    uint32_t Whi[2][8][4], Wlo[2][8][4];
    #pragma unroll
    for (int At = 0; At < 2; At++) {
        int mA = At * 16 + qr;
        int row0 = (mA >> 3) * 512 + j0 + (mA & 7);
        int mB = mA + 8;
        int row1 = (mB >> 3) * 512 + j0 + (mB & 7);
        #pragma unroll
        for (int ko = 0; ko < 8; ko++) {
            int kb = k0 + ko * 8 + qc;
            float v[4];
            v[0] = W[(size_t)row0 * HH + kb];
            v[1] = W[(size_t)row1 * HH + kb];
            v[2] = W[(size_t)row0 * HH + kb + 4];
            v[3] = W[(size_t)row1 * HH + kb + 4];
            #pragma unroll
            for (int r = 0; r < 4; r++) {
                float h_, l_;
                split_tf32(v[r], h_, l_);
                Whi[At][ko][r] = __float_as_uint(h_);
                Wlo[At][ko][r] = __float_as_uint(l_);
            }
        }
    }

    float cst[4] = {0.f, 0.f, 0.f, 0.f};  // cell state per batch-chunk

    for (int s = 0; s < TT; s++) {
        const int rb = s & 1, wb = rb ^ 1;
        const int tt = dir ? (TT - 1 - s) : s;
        const float* xpt = xp + (size_t)tt * BB * G4H;
        const float* hsrc = hst + (size_t)(rb * 2 + dir) * (BB * 1024);
        float* hdst = hst + (size_t)(wb * 2 + dir) * (BB * 1024);

        auto issue = [&](int ch2, int st) {
            const float* src0 = hsrc + (size_t)(ch2 * 16) * 1024;
            uint32_t base = sb + (uint32_t)st * HSTG;
            #pragma unroll
            for (int i = 0; i < 16; i++) {
                int sIdx = tid + i * 256;
                int row = sIdx >> 8, seg = sIdx & 255;
                cp16(base + (uint32_t)(row * HROW + seg * 4) * 4,
                     src0 + row * 1024 + seg * 4);
            }
            cp_commit();
        };

        issue(0, 0);
        #pragma unroll
        for (int ch = 0; ch < 4; ch++) {
            if (ch < 3) { issue(ch + 1, (ch + 1) & 1); cp_wait1(); }
            else cp_wait0();
            __syncthreads();

            float xgv[4] = {0.f, 0.f, 0.f, 0.f};
            if (tid < 128) {
                int b = ch * 16 + (tid >> 3);
                int j = j0 + (tid & 7);
                #pragma unroll
                for (int g = 0; g < 4; g++)
                    xgv[g] = xpt[b * G4H + g * HH + j];
            }

            float acc[2][2][4];
            #pragma unroll
            for (int At = 0; At < 2; At++)
                #pragma unroll
                for (int nt = 0; nt < 2; nt++)
                    #pragma unroll
                    for (int q = 0; q < 4; q++) acc[At][nt][q] = 0.0f;

            const float* Hc = Hs + (ch & 1) * (16 * HROW);
            #pragma unroll
            for (int ko = 0; ko < 8; ko++) {
                const int kw = (k0 + ko * 8 + qc) * 2;
                #pragma unroll
                for (int nt = 0; nt < 2; nt++) {
                    const float* p = Hc + (nt * 8 + qr) * HROW + kw;
                    float2 f0 = *reinterpret_cast<const float2*>(p);
                    float2 f1 = *reinterpret_cast<const float2*>(p + 8);
                    uint32_t bh0 = __float_as_uint(f0.x), bl0 = __float_as_uint(f0.y);
                    uint32_t bh1 = __float_as_uint(f1.x), bl1 = __float_as_uint(f1.y);
                    #pragma unroll
                    for (int At = 0; At < 2; At++) {
                        mma_tf32(acc[At][nt], Whi[At][ko], bh0, bh1);
                        mma_tf32(acc[At][nt], Wlo[At][ko], bh0, bh1);
                        mma_tf32(acc[At][nt], Whi[At][ko], bl0, bl1);
                    }
                }
            }

            // stage k-partials: Ps[wid][m(20)][n]
            #pragma unroll
            for (int At = 0; At < 2; At++)
                #pragma unroll
                for (int nt = 0; nt < 2; nt++) {
                    int m = At * 16 + qr, n = nt * 8 + 2 * qc;
                    *reinterpret_cast<float2*>(&Ps[wid * 640 + m * 20 + n]) =
                        make_float2(acc[At][nt][0], acc[At][nt][1]);
                    *reinterpret_cast<float2*>(&Ps[wid * 640 + (m + 8) * 20 + n]) =
                        make_float2(acc[At][nt][2], acc[At][nt][3]);
                }
            __syncthreads();

            if (tid < 128) {
                int m = tid >> 2, q = tid & 3;
                float4 sum = make_float4(0.f, 0.f, 0.f, 0.f);
                #pragma unroll
                for (int w = 0; w < 8; w++) {
                    float4 v = *reinterpret_cast<const float4*>(
                        &Ps[w * 640 + m * 20 + q * 4]);
                    sum.x += v.x; sum.y += v.y; sum.z += v.z; sum.w += v.w;
                }
                *reinterpret_cast<float4*>(&Gs[m * 20 + q * 4]) = sum;
            }
            __syncthreads();

            if (tid < 128) {
                int bI = tid >> 3, jl = tid & 7;
                int b = ch * 16 + bI;
                float gi = Gs[(0 * 8 + jl) * 20 + bI] + xgv[0];
                float gf = Gs[(1 * 8 + jl) * 20 + bI] + xgv[1];
                float gg = Gs[(2 * 8 + jl) * 20 + bI] + xgv[2];
                float go = Gs[(3 * 8 + jl) * 20 + bI] + xgv[3];
                float c = sigm(gf) * cst[ch] + sigm(gi) * tanhf(gg);
                cst[ch] = c;
                float hv = sigm(go) * tanhf(c);
                float hh_, hl_;
                split_tf32(hv, hh_, hl_);
                *reinterpret_cast<float2*>(&hdst[(size_t)b * 1024 + (j0 + jl) * 2]) =
                    make_float2(hh_, hl_);
                size_t o = (size_t)(tt * BB + b) * (2 * HH) + (size_t)dir * HH + j0 + jl;
                if (dosplit) { hb_hi[o] = hh_; hb_lo[o] = hl_; }
                else hout[o] = hv;
            }
        }

        __threadfence();
        __syncthreads();
        if (s + 1 < TT) {
            if (tid == 0) {
                atomicAdd(&bar[dir], 1u);
                unsigned target = 64u * (unsigned)(s + 1);
                volatile unsigned* p = bar + dir;
                while (*p < target) __nanosleep(64);
                __threadfence();
            }
            __syncthreads();
        }
    }
}

// ---------------- emissions ------------------------------------------------------
__global__ __launch_bounds__(128) void feats_kernel(
    const float* __restrict__ h, const float* __restrict__ Wout,
    const float* __restrict__ bout, float* __restrict__ feats)
{
    __shared__ __align__(16) float hs[4][2 * HH];
    int m0 = blockIdx.x * 4;
    int tid = threadIdx.x;
    for (int i = tid * 4; i < 4 * 2 * HH; i += 128 * 4)
        *reinterpret_cast<float4*>(&hs[0][i]) =
            *reinterpret_cast<const float4*>(&h[(size_t)m0 * 2 * HH + i]);
    __syncthreads();
    int r = tid >> 5, tag = tid & 31;
    const float* w = Wout + (size_t)tag * (2 * HH);
    float acc = 0.0f;
    #pragma unroll 4
    for (int k = 0; k < 2 * HH; k += 4) {
        float4 wv = *reinterpret_cast<const float4*>(&w[k]);
        float4 hv = *reinterpret_cast<const float4*>(&hs[r][k]);
        acc += wv.x * hv.x + wv.y * hv.y + wv.z * hv.z + wv.w * hv.w;
    }
    feats[(size_t)(m0 + r) * KK + tag] = acc + bout[tag];
}

// ---------------- Viterbi --------------------------------------------------------
__global__ __launch_bounds__(32) void viterbi_kernel(
    const float* __restrict__ feats, const float* __restrict__ trans,
    const float* __restrict__ startt, const float* __restrict__ stopt,
    float* __restrict__ out, int out_size)
{
    int b = blockIdx.x;
    int j = threadIdx.x;
    __shared__ unsigned char bp[TT - 1][KK];
    __shared__ int path[TT];

    float tr[KK];
    #pragma unroll
    for (int k = 0; k < KK; k++) tr[k] = trans[j * KK + k];

    float dp = startt[j] + feats[(size_t)b * KK + j];
    for (int t = 1; t < TT; t++) {
        float best = -INFINITY;
        int arg = 0;
        #pragma unroll
        for (int k = 0; k < KK; k++) {
            float v = tr[k] + __shfl_sync(0xffffffffu, dp, k);
            if (v > best) { best = v; arg = k; }
        }
        bp[t - 1][j] = (unsigned char)arg;
        dp = best + feats[((size_t)t * BB + b) * KK + j];
    }
    dp += stopt[j];

    float bv = dp; int bi = j;
    #pragma unroll
    for (int off = 16; off; off >>= 1) {
        float ov = __shfl_down_sync(0xffffffffu, bv, off);
        int   oi = __shfl_down_sync(0xffffffffu, bi, off);
        if (ov > bv || (ov == bv && oi < bi)) { bv = ov; bi = oi; }
    }
    bv = __shfl_sync(0xffffffffu, bv, 0);
    bi = __shfl_sync(0xffffffffu, bi, 0);

    if (j == 0) {
        path[TT - 1] = bi;
        int tag = bi;
        for (int t = TT - 2; t >= 0; t--) {
            tag = bp[t][tag];
            path[t] = tag;
        }
    }
    __syncwarp();

    int pathsOff = out_size - TT * BB;
    if (pathsOff >= (int)BB) {
        if (j == 0) out[b] = bv;
    } else if (pathsOff < 0) {
        if (j == 0 && b < out_size) out[b] = bv;
        return;
    }
    for (int t = j; t < TT; t += 32)
        out[pathsOff + t * BB + b] = (float)path[t];
}

// ---------------- launch ---------------------------------------------------------
extern "C" void kernel_launch(void* const* d_in, const int* in_sizes, int n_in,
                              void* d_out, int out_size) {
    const int*   sent    = (const int*)d_in[0];
    const float* emb     = (const float*)d_in[1];
    const float* wih_l0f = (const float*)d_in[2];
    const float* whh_l0f = (const float*)d_in[3];
    const float* bih_l0f = (const float*)d_in[4];
    const float* bhh_l0f = (const float*)d_in[5];
    const float* wih_l0r = (const float*)d_in[6];
    const float* whh_l0r = (const float*)d_in[7];
    const float* bih_l0r = (const float*)d_in[8];
    const float* bhh_l0r = (const float*)d_in[9];
    const float* wih_l1f = (const float*)d_in[10];
    const float* whh_l1f = (const float*)d_in[11];
    const float* bih_l1f = (const float*)d_in[12];
    const float* bhh_l1f = (const float*)d_in[13];
    const float* wih_l1r = (const float*)d_in[14];
    const float* whh_l1r = (const float*)d_in[15];
    const float* bih_l1r = (const float*)d_in[16];
    const float* bhh_l1r = (const float*)d_in[17];
    const float* W_out   = (const float*)d_in[18];
    const float* b_out   = (const float*)d_in[19];
    const float* transit = (const float*)d_in[20];
    const float* start_t = (const float*)d_in[21];
    const float* stop_t  = (const float*)d_in[22];

    float *xpf, *xpr, *hbuf, *feats, *hst;
    unsigned* bar;
    cudaGetSymbolAddress((void**)&xpf,   g_xpf);
    cudaGetSymbolAddress((void**)&xpr,   g_xpr);
    cudaGetSymbolAddress((void**)&hbuf,  g_hbuf);
    cudaGetSymbolAddress((void**)&feats, g_feats);
    cudaGetSymbolAddress((void**)&hst,   g_hst2);
    cudaGetSymbolAddress((void**)&bar,   g_bar);
    float *as, *hsx, *w0f, *w0r, *w1f, *w1r;
    cudaGetSymbolAddress((void**)&as,  g_as);
    cudaGetSymbolAddress((void**)&hsx, g_hs);
    cudaGetSymbolAddress((void**)&w0f, g_w0f);
    cudaGetSymbolAddress((void**)&w0r, g_w0r);
    cudaGetSymbolAddress((void**)&w1f, g_w1f);
    cudaGetSymbolAddress((void**)&w1r, g_w1r);
    const size_t ASZ = (size_t)MROWS*EE, HSZ = (size_t)MROWS*2*HH;
    const size_t W0SZ = (size_t)G4H*EE,  W1SZ = (size_t)G4H*2*HH;

    cudaFuncSetAttribute(tf32_gemm,
                         cudaFuncAttributeMaxDynamicSharedMemorySize, GEMM_SMEM);
    cudaFuncSetAttribute(lstm_mma2_kernel,
                         cudaFuncAttributeMaxDynamicSharedMemorySize, LSTM3_SMEM);

    // 1) embedding (fused gather + tf32 split)
    embed_split_kernel<<<(TT * BB * (EE / 4) + 255) / 256, 256>>>(
        sent, emb, as, as + ASZ);

    // 2) split input-projection weights
    split2_kernel<<<(int)(W0SZ/4 + 255)/256, 256>>>(wih_l0f, w0f, w0f + W0SZ, (int)(W0SZ/4));
    split2_kernel<<<(int)(W0SZ/4 + 255)/256, 256>>>(wih_l0r, w0r, w0r + W0SZ, (int)(W0SZ/4));
    split2_kernel<<<(int)(W1SZ/4 + 255)/256, 256>>>(wih_l1f, w1f, w1f + W1SZ, (int)(W1SZ/4));
    split2_kernel<<<(int)(W1SZ/4 + 255)/256, 256>>>(wih_l1r, w1r, w1r + W1SZ, (int)(W1SZ/4));

    dim3 gg(G4H / 128, MROWS / 128);

    // 3) layer-0 input projections
    tf32_gemm<<<gg, 256, GEMM_SMEM>>>(as, as + ASZ, w0f, w0f + W0SZ,
                                      bih_l0f, bhh_l0f, xpf, EE);
    tf32_gemm<<<gg, 256, GEMM_SMEM>>>(as, as + ASZ, w0r, w0r + W0SZ,
                                      bih_l0r, bhh_l0r, xpr, EE);

    // 4) layer-0 recurrence (k-split tensor-core LSTM); writes hbuf splits
    cudaMemsetAsync(hst, 0, sizeof(float) * 2 * 2 * BB * 1024);
    cudaMemsetAsync(bar, 0, sizeof(unsigned) * 2);
    lstm_mma2_kernel<<<128, 256, LSTM3_SMEM>>>(xpf, xpr, whh_l0f, whh_l0r,
                                               hbuf, hst,
                                               hsx, hsx + HSZ, bar, 1);

    // 5) layer-1 input projections (K = 2H)
    tf32_gemm<<<gg, 256, GEMM_SMEM>>>(hsx, hsx + HSZ, w1f, w1f + W1SZ,
                                      bih_l1f, bhh_l1f, xpf, 2 * HH);
    tf32_gemm<<<gg, 256, GEMM_SMEM>>>(hsx, hsx + HSZ, w1r, w1r + W1SZ,
                                      bih_l1r, bhh_l1r, xpr, 2 * HH);

    // 6) layer-1 recurrence (writes hbuf fp32 for feats)
    cudaMemsetAsync(hst, 0, sizeof(float) * 2 * 2 * BB * 1024);
    cudaMemsetAsync(bar, 0, sizeof(unsigned) * 2);
    lstm_mma2_kernel<<<128, 256, LSTM3_SMEM>>>(xpf, xpr, whh_l1f, whh_l1r,
                                               hbuf, hst,
                                               hsx, hsx + HSZ, bar, 0);

    // 7) emissions
    feats_kernel<<<MROWS / 4, 128>>>(hbuf, W_out, b_out, feats);

    // 8) Viterbi decode + output write
    viterbi_kernel<<<BB, 32>>>(feats, transit, start_t, stop_t, (float*)d_out, out_size);
}

// round 11
// speedup vs baseline: 1.0963x; 1.0003x over previous
#include <cuda_runtime.h>
#include <cstdint>
#include <math.h>

#define TT 256
#define BB 64
#define EE 256
#define HH 512
#define KK 32
#define G4H 2048
#define MROWS (TT*BB)

// ---------------- scratch (static device allocations) ---------------------------
__device__ float    g_xpf[MROWS*G4H];
__device__ float    g_xpr[MROWS*G4H];
__device__ float    g_hbuf[MROWS*2*HH];
__device__ float    g_feats[MROWS*KK];
__device__ float    g_hst[2*2*BB*HH];        // [buf][dir][B][H] fp32 h state
__device__ unsigned g_bar[2];
__device__ __align__(16) float g_as[2][MROWS*EE];
__device__ __align__(16) float g_hs[2][MROWS*2*HH];
__device__ __align__(16) float g_w0f[2][G4H*EE];
__device__ __align__(16) float g_w0r[2][G4H*EE];
__device__ __align__(16) float g_w1f[2][G4H*2*HH];
__device__ __align__(16) float g_w1r[2][G4H*2*HH];

extern __shared__ __align__(16) char dynsmem[];

// ---------------- helpers --------------------------------------------------------
__device__ __forceinline__ float sigm(float x) { return 1.0f / (1.0f + expf(-x)); }

__device__ __forceinline__ void split_tf32(float x, float& hi, float& lo) {
    uint32_t h;
    asm("cvt.rna.tf32.f32 %0, %1;" : "=r"(h) : "f"(x));
    hi = __uint_as_float(h);
    float r = x - hi;
    uint32_t l;
    asm("cvt.rna.tf32.f32 %0, %1;" : "=r"(l) : "f"(r));
    lo = __uint_as_float(l);
}
__device__ __forceinline__ uint32_t smem_u32(const void* p) {
    uint32_t a;
    asm("{ .reg .u64 t; cvta.to.shared.u64 t, %1; cvt.u32.u64 %0, t; }"
        : "=r"(a) : "l"(p));
    return a;
}
__device__ __forceinline__ void cp16(uint32_t dst, const void* src) {
    asm volatile("cp.async.cg.shared.global [%0], [%1], 16;"
                 :: "r"(dst), "l"(src) : "memory");
}
__device__ __forceinline__ void cp_commit() {
    asm volatile("cp.async.commit_group;" ::: "memory");
}
__device__ __forceinline__ void cp_wait1() {
    asm volatile("cp.async.wait_group 1;" ::: "memory");
}
__device__ __forceinline__ void cp_wait0() {
    asm volatile("cp.async.wait_group 0;" ::: "memory");
}
__device__ __forceinline__ void mma_tf32(float* d, const uint32_t* a,
                                         uint32_t b0, uint32_t b1) {
    asm volatile(
        "mma.sync.aligned.m16n8k8.row.col.f32.tf32.tf32.f32 "
        "{%0,%1,%2,%3}, {%4,%5,%6,%7}, {%8,%9}, {%0,%1,%2,%3};"
        : "+f"(d[0]), "+f"(d[1]), "+f"(d[2]), "+f"(d[3])
        : "r"(a[0]), "r"(a[1]), "r"(a[2]), "r"(a[3]), "r"(b0), "r"(b1));
}

// ---------------- tf32 split kernels ---------------------------------------------
__global__ void split2_kernel(const float* __restrict__ in, float* __restrict__ oh,
                              float* __restrict__ ol, int n4) {
    int i = blockIdx.x * blockDim.x + threadIdx.x;
    if (i >= n4) return;
    float4 a = reinterpret_cast<const float4*>(in)[i];
    float4 h, l;
    split_tf32(a.x, h.x, l.x);
    split_tf32(a.y, h.y, l.y);
    split_tf32(a.z, h.z, l.z);
    split_tf32(a.w, h.w, l.w);
    reinterpret_cast<float4*>(oh)[i] = h;
    reinterpret_cast<float4*>(ol)[i] = l;
}

__global__ void embed_split_kernel(const int* __restrict__ sent,
                                   const float* __restrict__ emb,
                                   float* __restrict__ oh, float* __restrict__ ol) {
    int i = blockIdx.x * blockDim.x + threadIdx.x;
    int total = TT * BB * (EE / 4);
    if (i >= total) return;
    int tb = i >> 6, e4 = i & 63;
    int v = sent[tb];
    float4 a = reinterpret_cast<const float4*>(emb + (size_t)v * EE)[e4];
    float4 h, l;
    split_tf32(a.x, h.x, l.x);
    split_tf32(a.y, h.y, l.y);
    split_tf32(a.z, h.z, l.z);
    split_tf32(a.w, h.w, l.w);
    reinterpret_cast<float4*>(oh)[i] = h;
    reinterpret_cast<float4*>(ol)[i] = l;
}

// ---------------- 3xTF32 mma.sync GEMM (validated round 4) ----------------------
#define TPAD 20
#define TILE_F (128 * TPAD)
#define STAGE_F (4 * TILE_F)
#define GEMM_SMEM (2 * STAGE_F * 4)

__global__ __launch_bounds__(256) void tf32_gemm(
    const float* __restrict__ Ah, const float* __restrict__ Al,
    const float* __restrict__ Wh, const float* __restrict__ Wl,
    const float* __restrict__ bi1, const float* __restrict__ bi2,
    float* __restrict__ C, int K)
{
    float* smem = reinterpret_cast<float*>(dynsmem);
    const uint32_t sb = smem_u32(smem);
    const int tid = threadIdx.x, lane = tid & 31, wid = tid >> 5;
    const int wm = wid & 1, wn = wid >> 1;
    const int bn = blockIdx.x * 128, bm = blockIdx.y * 128;
    const int nch = K >> 4;
    const int qr = lane >> 2, qc = lane & 3;

    float acc[4][4][4];
    #pragma unroll
    for (int mi = 0; mi < 4; mi++)
        #pragma unroll
        for (int ni = 0; ni < 4; ni++)
            #pragma unroll
            for (int q = 0; q < 4; q++) acc[mi][ni][q] = 0.0f;

    auto issue = [&](int c, int st) {
        #pragma unroll
        for (int i = 0; i < 8; i++) {
            int s = tid + i * 256;
            int tile = s >> 9;
            int r = (s >> 2) & 127;
            int sub = s & 3;
            const float* g;
            if (tile == 0)      g = Ah + (size_t)(bm + r) * K + c * 16 + sub * 4;
            else if (tile == 1) g = Al + (size_t)(bm + r) * K + c * 16 + sub * 4;
            else if (tile == 2) g = Wh + (size_t)(bn + r) * K + c * 16 + sub * 4;
            else                g = Wl + (size_t)(bn + r) * K + c * 16 + sub * 4;
            uint32_t d = sb + (uint32_t)(st * STAGE_F + tile * TILE_F + r * TPAD + sub * 4) * 4;
            cp16(d, g);
        }
        cp_commit();
    };

    issue(0, 0);

    for (int c = 0; c < nch; c++) {
        const int st = c & 1;
        if (c + 1 < nch) { issue(c + 1, st ^ 1); cp_wait1(); }
        else cp_wait0();
        __syncthreads();

        const float* Ah_s = smem + st * STAGE_F;
        const float* Al_s = Ah_s + TILE_F;
        const float* Wh_s = Ah_s + 2 * TILE_F;
        const float* Wl_s = Ah_s + 3 * TILE_F;

        #pragma unroll
        for (int s8 = 0; s8 < 16; s8 += 8) {
            #pragma unroll
            for (int t = 0; t < 3; t++) {
                const float* At = (t == 2) ? Al_s : Ah_s;
                const float* Wt = (t == 1) ? Wl_s : Wh_s;
                uint32_t a[4][4];
                #pragma unroll
                for (int mi = 0; mi < 4; mi++) {
                    int m = wm * 64 + mi * 16 + qr;
                    const uint32_t* p =
                        reinterpret_cast<const uint32_t*>(At + m * TPAD + s8 + qc);
                    a[mi][0] = p[0];
                    a[mi][2] = p[4];
                    const uint32_t* p8 =
                        reinterpret_cast<const uint32_t*>(At + (m + 8) * TPAD + s8 + qc);
                    a[mi][1] = p8[0];
                    a[mi][3] = p8[4];
                }
                #pragma unroll
                for (int ni = 0; ni < 4; ni++) {
                    int n = wn * 32 + ni * 8 + qr;
                    const uint32_t* p =
                        reinterpret_cast<const uint32_t*>(Wt + n * TPAD + s8 + qc);
                    uint32_t b0 = p[0], b1 = p[4];
                    #pragma unroll
                    for (int mi = 0; mi < 4; mi++)
                        mma_tf32(acc[mi][ni], a[mi], b0, b1);
                }
            }
        }
        __syncthreads();
    }

    #pragma unroll
    for (int ni = 0; ni < 4; ni++) {
        int col = bn + wn * 32 + ni * 8 + 2 * qc;
        float2 s1 = *reinterpret_cast<const float2*>(bi1 + col);
        float2 s2 = *reinterpret_cast<const float2*>(bi2 + col);
        float bx = s1.x + s2.x, by = s1.y + s2.y;
        #pragma unroll
        for (int mi = 0; mi < 4; mi++) {
            int row = bm + wm * 64 + mi * 16 + qr;
            float2 v0 = make_float2(acc[mi][ni][0] + bx, acc[mi][ni][1] + by);
            float2 v1 = make_float2(acc[mi][ni][2] + bx, acc[mi][ni][3] + by);
            *reinterpret_cast<float2*>(&C[(size_t)row * G4H + col]) = v0;
            *reinterpret_cast<float2*>(&C[(size_t)(row + 8) * G4H + col]) = v1;
        }
    }
}

// ---------------- persistent LSTM v4: one-pass step, per-warp sync --------------
// 128 blocks = dir(2) x 64 j-groups, 256 threads (8 warps).
// Warp w owns K-slice [64w,64w+64); W_hh tf32 hi/lo frags in 128 regs.
// h state in global is PLAIN fp32; each warp cp.asyncs ONLY its 64-col slice of
// all 64 batches (16KB = 1024 cp16s) and waits on its own group (no block sync
// before MMA). tf32 hi/lo split of h happens in registers at fragment-load time.
// One partial staging + one reduce + cell update per step (3 syncthreads).
#define HR 516
#define PSD 68
#define OFF_PS (64 * HR * 4)                 // 132096
#define PS_W   (32 * PSD)                    // floats per warp
#define OFF_GS (OFF_PS + 8 * PS_W * 4)       // 201728
#define LSTM4_SMEM (OFF_GS + 32 * PSD * 4)   // 210432 B

__global__ __launch_bounds__(256, 1) void lstm_mma3_kernel(
    const float* __restrict__ xpf, const float* __restrict__ xpr,
    const float* __restrict__ whf, const float* __restrict__ whr,
    float* __restrict__ hout, float* hst,
    float* __restrict__ hb_hi, float* __restrict__ hb_lo,
    unsigned* bar, int dosplit)
{
    float* Hs = reinterpret_cast<float*>(dynsmem);
    float* Ps = reinterpret_cast<float*>(dynsmem + OFF_PS);
    float* Gs = reinterpret_cast<float*>(dynsmem + OFF_GS);
    const uint32_t sb = smem_u32(dynsmem);
    const int tid = threadIdx.x, lane = tid & 31, wid = tid >> 5;
    const int dir = blockIdx.x >> 6, sub = blockIdx.x & 63, j0 = sub * 8;
    const float* W  = dir ? whr : whf;
    const float* xp = dir ? xpr : xpf;
    const int qr = lane >> 2, qc = lane & 3;
    const int k0 = wid * 64;

    // gather W_hh fragments (hi & lo) into registers — once per layer
    uint32_t Whi[2][8][4], Wlo[2][8][4];
    #pragma unroll
    for (int At = 0; At < 2; At++) {
        int mA = At * 16 + qr;
        int row0 = (mA >> 3) * 512 + j0 + (mA & 7);
        int mB = mA + 8;
        int row1 = (mB >> 3) * 512 + j0 + (mB & 7);
        #pragma unroll
        for (int ko = 0; ko < 8; ko++) {
            int kb = k0 + ko * 8 + qc;
            float v[4];
            v[0] = W[(size_t)row0 * HH + kb];
            v[1] = W[(size_t)row1 * HH + kb];
            v[2] = W[(size_t)row0 * HH + kb + 4];
            v[3] = W[(size_t)row1 * HH + kb + 4];
            #pragma unroll
            for (int r = 0; r < 4; r++) {
                float h_, l_;
                split_tf32(v[r], h_, l_);
                Whi[At][ko][r] = __float_as_uint(h_);
                Wlo[At][ko][r] = __float_as_uint(l_);
            }
        }
    }

    // two cells per thread: (batch, j) = (cb, j0 + cj)
    const int cb0 = tid >> 3,          cj0 = tid & 7;
    const int cb1 = (tid + 256) >> 3,  cj1 = tid & 7;
    float cc0 = 0.0f, cc1 = 0.0f;

    for (int s = 0; s < TT; s++) {
        const int rb = s & 1, wb = rb ^ 1;
        const int tt = dir ? (TT - 1 - s) : s;
        const float* xpt = xp + (size_t)tt * BB * G4H;
        const float* hsrc = hst + (size_t)(rb * 2 + dir) * (BB * HH);
        float* hdst = hst + (size_t)(wb * 2 + dir) * (BB * HH);

        // prefetch x-projection gate values for this thread's two cells (DRAM)
        float xg0[4], xg1[4];
        #pragma unroll
        for (int g = 0; g < 4; g++) {
            xg0[g] = xpt[cb0 * G4H + g * HH + j0 + cj0];
            xg1[g] = xpt[cb1 * G4H + g * HH + j0 + cj1];
        }

        // per-warp cp.async of this warp's k-slice: 64 rows x 64 floats = 16KB
        // (1024 cp16 ops: row = idx>>4, seg = idx&15 covers all 64 floats/row)
        #pragma unroll
        for (int i = 0; i < 32; i++) {
            int idx = lane + i * 32;
            int row = idx >> 4, seg = idx & 15;
            cp16(sb + (uint32_t)(row * HR + k0 + seg * 4) * 4,
                 hsrc + (size_t)row * HH + k0 + seg * 4);
        }
        cp_commit();
        cp_wait0();
        __syncwarp();

        // full-batch MMA over this warp's k-slice (h split to tf32 in regs)
        float acc[2][8][4];
        #pragma unroll
        for (int At = 0; At < 2; At++)
            #pragma unroll
            for (int nt = 0; nt < 8; nt++)
                #pragma unroll
                for (int q = 0; q < 4; q++) acc[At][nt][q] = 0.0f;

        #pragma unroll
        for (int ko = 0; ko < 8; ko++) {
            #pragma unroll
            for (int nt = 0; nt < 8; nt++) {
                const float* p = Hs + (nt * 8 + qr) * HR + k0 + ko * 8 + qc;
                float b0v = p[0], b1v = p[4];
                float bh0f, bl0f, bh1f, bl1f;
                split_tf32(b0v, bh0f, bl0f);
                split_tf32(b1v, bh1f, bl1f);
                uint32_t bh0 = __float_as_uint(bh0f), bl0 = __float_as_uint(bl0f);
                uint32_t bh1 = __float_as_uint(bh1f), bl1 = __float_as_uint(bl1f);
                #pragma unroll
                for (int At = 0; At < 2; At++) {
                    mma_tf32(acc[At][nt], Whi[At][ko], bh0, bh1);
                    mma_tf32(acc[At][nt], Wlo[At][ko], bh0, bh1);
                    mma_tf32(acc[At][nt], Whi[At][ko], bl0, bl1);
                }
            }
        }

        // stage partials: Ps[wid][m (stride PSD)][n]
        float* Pw = Ps + wid * PS_W;
        #pragma unroll
        for (int At = 0; At < 2; At++)
            #pragma unroll
            for (int nt = 0; nt < 8; nt++) {
                int m = At * 16 + qr, n = nt * 8 + 2 * qc;
                *reinterpret_cast<float2*>(&Pw[m * PSD + n]) =
                    make_float2(acc[At][nt][0], acc[At][nt][1]);
                *reinterpret_cast<float2*>(&Pw[(m + 8) * PSD + n]) =
                    make_float2(acc[At][nt][2], acc[At][nt][3]);
            }
        __syncthreads();

        // reduce 8 k-partials: thread -> (m = tid>>3, n0 = (tid&7)*8)
        {
            int m = tid >> 3, n0 = (tid & 7) * 8;
            float4 s0 = make_float4(0.f, 0.f, 0.f, 0.f);
            float4 s1 = make_float4(0.f, 0.f, 0.f, 0.f);
            #pragma unroll
            for (int w = 0; w < 8; w++) {
                const float* q = Ps + w * PS_W + m * PSD + n0;
                float4 a = *reinterpret_cast<const float4*>(q);
                float4 b = *reinterpret_cast<const float4*>(q + 4);
                s0.x += a.x; s0.y += a.y; s0.z += a.z; s0.w += a.w;
                s1.x += b.x; s1.y += b.y; s1.z += b.z; s1.w += b.w;
            }
            *reinterpret_cast<float4*>(&Gs[m * PSD + n0]) = s0;
            *reinterpret_cast<float4*>(&Gs[m * PSD + n0 + 4]) = s1;
        }
        __syncthreads();

        // cell updates (2 per thread); Gs[m = gate*8 + jl][n = b]
        {
            float gi = Gs[(0 * 8 + cj0) * PSD + cb0] + xg0[0];
            float gf = Gs[(1 * 8 + cj0) * PSD + cb0] + xg0[1];
            float gg = Gs[(2 * 8 + cj0) * PSD + cb0] + xg0[2];
            float go = Gs[(3 * 8 + cj0) * PSD + cb0] + xg0[3];
            cc0 = sigm(gf) * cc0 + sigm(gi) * tanhf(gg);
            float hv = sigm(go) * tanhf(cc0);
            hdst[(size_t)cb0 * HH + j0 + cj0] = hv;
            size_t o = (size_t)(tt * BB + cb0) * (2 * HH) + (size_t)dir * HH + j0 + cj0;
            if (dosplit) {
                float hh_, hl_;
                split_tf32(hv, hh_, hl_);
                hb_hi[o] = hh_; hb_lo[o] = hl_;
            } else hout[o] = hv;
        }
        {
            float gi = Gs[(0 * 8 + cj1) * PSD + cb1] + xg1[0];
            float gf = Gs[(1 * 8 + cj1) * PSD + cb1] + xg1[1];
            float gg = Gs[(2 * 8 + cj1) * PSD + cb1] + xg1[2];
            float go = Gs[(3 * 8 + cj1) * PSD + cb1] + xg1[3];
            cc1 = sigm(gf) * cc1 + sigm(gi) * tanhf(gg);
            float hv = sigm(go) * tanhf(cc1);
            hdst[(size_t)cb1 * HH + j0 + cj1] = hv;
            size_t o = (size_t)(tt * BB + cb1) * (2 * HH) + (size_t)dir * HH + j0 + cj1;
            if (dosplit) {
                float hh_, hl_;
                split_tf32(hv, hh_, hl_);
                hb_hi[o] = hh_; hb_lo[o] = hl_;
            } else hout[o] = hv;
        }

        __threadfence();
        __syncthreads();
        if (s + 1 < TT) {
            if (tid == 0) {
                atomicAdd(&bar[dir], 1u);
                unsigned target = 64u * (unsigned)(s + 1);
                volatile unsigned* p = bar + dir;
                while (*p < target) __nanosleep(64);
                __threadfence();
            }
            __syncthreads();
        }
    }
}

// ---------------- emissions ------------------------------------------------------
__global__ __launch_bounds__(128) void feats_kernel(
    const float* __restrict__ h, const float* __restrict__ Wout,
    const float* __restrict__ bout, float* __restrict__ feats)
{
    __shared__ __align__(16) float hs[4][2 * HH];
    int m0 = blockIdx.x * 4;
    int tid = threadIdx.x;
    for (int i = tid * 4; i < 4 * 2 * HH; i += 128 * 4)
        *reinterpret_cast<float4*>(&hs[0][i]) =
            *reinterpret_cast<const float4*>(&h[(size_t)m0 * 2 * HH + i]);
    __syncthreads();
    int r = tid >> 5, tag = tid & 31;
    const float* w = Wout + (size_t)tag * (2 * HH);
    float acc = 0.0f;
    #pragma unroll 4
    for (int k = 0; k < 2 * HH; k += 4) {
        float4 wv = *reinterpret_cast<const float4*>(&w[k]);
        float4 hv = *reinterpret_cast<const float4*>(&hs[r][k]);
        acc += wv.x * hv.x + wv.y * hv.y + wv.z * hv.z + wv.w * hv.w;
    }
    feats[(size_t)(m0 + r) * KK + tag] = acc + bout[tag];
}

// ---------------- Viterbi --------------------------------------------------------
__global__ __launch_bounds__(32) void viterbi_kernel(
    const float* __restrict__ feats, const float* __restrict__ trans,
    const float* __restrict__ startt, const float* __restrict__ stopt,
    float* __restrict__ out, int out_size)
{
    int b = blockIdx.x;
    int j = threadIdx.x;
    __shared__ unsigned char bp[TT - 1][KK];
    __shared__ int path[TT];

    float tr[KK];
    #pragma unroll
    for (int k = 0; k < KK; k++) tr[k] = trans[j * KK + k];

    float dp = startt[j] + feats[(size_t)b * KK + j];
    for (int t = 1; t < TT; t++) {
        float best = -INFINITY;
        int arg = 0;
        #pragma unroll
        for (int k = 0; k < KK; k++) {
            float v = tr[k] + __shfl_sync(0xffffffffu, dp, k);
            if (v > best) { best = v; arg = k; }
        }
        bp[t - 1][j] = (unsigned char)arg;
        dp = best + feats[((size_t)t * BB + b) * KK + j];
    }
    dp += stopt[j];

    float bv = dp; int bi = j;
    #pragma unroll
    for (int off = 16; off; off >>= 1) {
        float ov = __shfl_down_sync(0xffffffffu, bv, off);
        int   oi = __shfl_down_sync(0xffffffffu, bi, off);
        if (ov > bv || (ov == bv && oi < bi)) { bv = ov; bi = oi; }
    }
    bv = __shfl_sync(0xffffffffu, bv, 0);
    bi = __shfl_sync(0xffffffffu, bi, 0);

    if (j == 0) {
        path[TT - 1] = bi;
        int tag = bi;
        for (int t = TT - 2; t >= 0; t--) {
            tag = bp[t][tag];
            path[t] = tag;
        }
    }
    __syncwarp();

    int pathsOff = out_size - TT * BB;
    if (pathsOff >= (int)BB) {
        if (j == 0) out[b] = bv;
    } else if (pathsOff < 0) {
        if (j == 0 && b < out_size) out[b] = bv;
        return;
    }
    for (int t = j; t < TT; t += 32)
        out[pathsOff + t * BB + b] = (float)path[t];
}

// ---------------- launch ---------------------------------------------------------
extern "C" void kernel_launch(void* const* d_in, const int* in_sizes, int n_in,
                              void* d_out, int out_size) {
    const int*   sent    = (const int*)d_in[0];
    const float* emb     = (const float*)d_in[1];
    const float* wih_l0f = (const float*)d_in[2];
    const float* whh_l0f = (const float*)d_in[3];
    const float* bih_l0f = (const float*)d_in[4];
    const float* bhh_l0f = (const float*)d_in[5];
    const float* wih_l0r = (const float*)d_in[6];
    const float* whh_l0r = (const float*)d_in[7];
    const float* bih_l0r = (const float*)d_in[8];
    const float* bhh_l0r = (const float*)d_in[9];
    const float* wih_l1f = (const float*)d_in[10];
    const float* whh_l1f = (const float*)d_in[11];
    const float* bih_l1f = (const float*)d_in[12];
    const float* bhh_l1f = (const float*)d_in[13];
    const float* wih_l1r = (const float*)d_in[14];
    const float* whh_l1r = (const float*)d_in[15];
    const float* bih_l1r = (const float*)d_in[16];
    const float* bhh_l1r = (const float*)d_in[17];
    const float* W_out   = (const float*)d_in[18];
    const float* b_out   = (const float*)d_in[19];
    const float* transit = (const float*)d_in[20];
    const float* start_t = (const float*)d_in[21];
    const float* stop_t  = (const float*)d_in[22];

    float *xpf, *xpr, *hbuf, *feats, *hst;
    unsigned* bar;
    cudaGetSymbolAddress((void**)&xpf,   g_xpf);
    cudaGetSymbolAddress((void**)&xpr,   g_xpr);
    cudaGetSymbolAddress((void**)&hbuf,  g_hbuf);
    cudaGetSymbolAddress((void**)&feats, g_feats);
    cudaGetSymbolAddress((void**)&hst,   g_hst);
    cudaGetSymbolAddress((void**)&bar,   g_bar);
    float *as, *hsx, *w0f, *w0r, *w1f, *w1r;
    cudaGetSymbolAddress((void**)&as,  g_as);
    cudaGetSymbolAddress((void**)&hsx, g_hs);
    cudaGetSymbolAddress((void**)&w0f, g_w0f);
    cudaGetSymbolAddress((void**)&w0r, g_w0r);
    cudaGetSymbolAddress((void**)&w1f, g_w1f);
    cudaGetSymbolAddress((void**)&w1r, g_w1r);
    const size_t ASZ = (size_t)MROWS*EE, HSZ = (size_t)MROWS*2*HH;
    const size_t W0SZ = (size_t)G4H*EE,  W1SZ = (size_t)G4H*2*HH;

    cudaFuncSetAttribute(tf32_gemm,
                         cudaFuncAttributeMaxDynamicSharedMemorySize, GEMM_SMEM);
    cudaFuncSetAttribute(lstm_mma3_kernel,
                         cudaFuncAttributeMaxDynamicSharedMemorySize, LSTM4_SMEM);

    // 1) embedding (fused gather + tf32 split)
    embed_split_kernel<<<(TT * BB * (EE / 4) + 255) / 256, 256>>>(
        sent, emb, as, as + ASZ);

    // 2) split input-projection weights
    split2_kernel<<<(int)(W0SZ/4 + 255)/256, 256>>>(wih_l0f, w0f, w0f + W0SZ, (int)(W0SZ/4));
    split2_kernel<<<(int)(W0SZ/4 + 255)/256, 256>>>(wih_l0r, w0r, w0r + W0SZ, (int)(W0SZ/4));
    split2_kernel<<<(int)(W1SZ/4 + 255)/256, 256>>>(wih_l1f, w1f, w1f + W1SZ, (int)(W1SZ/4));
    split2_kernel<<<(int)(W1SZ/4 + 255)/256, 256>>>(wih_l1r, w1r, w1r + W1SZ, (int)(W1SZ/4));

    dim3 gg(G4H / 128, MROWS / 128);

    // 3) layer-0 input projections
    tf32_gemm<<<gg, 256, GEMM_SMEM>>>(as, as + ASZ, w0f, w0f + W0SZ,
                                      bih_l0f, bhh_l0f, xpf, EE);
    tf32_gemm<<<gg, 256, GEMM_SMEM>>>(as, as + ASZ, w0r, w0r + W0SZ,
                                      bih_l0r, bhh_l0r, xpr, EE);

    // 4) layer-0 recurrence (one-pass tensor-core LSTM); writes hbuf splits
    cudaMemsetAsync(hst, 0, sizeof(float) * 2 * 2 * BB * HH);
    cudaMemsetAsync(bar, 0, sizeof(unsigned) * 2);
    lstm_mma3_kernel<<<128, 256, LSTM4_SMEM>>>(xpf, xpr, whh_l0f, whh_l0r,
                                               hbuf, hst,
                                               hsx, hsx + HSZ, bar, 1);

    // 5) layer-1 input projections (K = 2H)
    tf32_gemm<<<gg, 256, GEMM_SMEM>>>(hsx, hsx + HSZ, w1f, w1f + W1SZ,
                                      bih_l1f, bhh_l1f, xpf, 2 * HH);
    tf32_gemm<<<gg, 256, GEMM_SMEM>>>(hsx, hsx + HSZ, w1r, w1r + W1SZ,
                                      bih_l1r, bhh_l1r, xpr, 2 * HH);

    // 6) layer-1 recurrence (writes hbuf fp32 for feats)
    cudaMemsetAsync(hst, 0, sizeof(float) * 2 * 2 * BB * HH);
    cudaMemsetAsync(bar, 0, sizeof(unsigned) * 2);
    lstm_mma3_kernel<<<128, 256, LSTM4_SMEM>>>(xpf, xpr, whh_l1f, whh_l1r,
                                               hbuf, hst,
                                               hsx, hsx + HSZ, bar, 0);

    // 7) emissions
    feats_kernel<<<MROWS / 4, 128>>>(hbuf, W_out, b_out, feats);

    // 8) Viterbi decode + output write
    viterbi_kernel<<<BB, 32>>>(feats, transit, start_t, stop_t, (float*)d_out, out_size);
}

// round 12
// speedup vs baseline: 1.1496x; 1.0486x over previous
#include <cuda_runtime.h>
#include <cstdint>
#include <math.h>

#define TT 256
#define BB 64
#define EE 256
#define HH 512
#define KK 32
#define G4H 2048
#define MROWS (TT*BB)

// ---------------- scratch (static device allocations) ---------------------------
__device__ float    g_xpf[MROWS*G4H];
__device__ float    g_xpr[MROWS*G4H];
__device__ float    g_feats[MROWS*KK];
__device__ float    g_hst[2*2*BB*HH];        // [buf][dir][B][H] fp32 h state
__device__ unsigned g_bar[2];
__device__ __align__(16) float g_as[2][MROWS*EE];
__device__ __align__(16) float g_hs[2][MROWS*2*HH];   // splits: L0 out, then L1 out
__device__ __align__(16) float g_w0f[2][G4H*EE];
__device__ __align__(16) float g_w0r[2][G4H*EE];
__device__ __align__(16) float g_w1f[2][G4H*2*HH];
__device__ __align__(16) float g_w1r[2][G4H*2*HH];
__device__ __align__(16) float g_wo[2][KK*2*HH];      // W_out splits

extern __shared__ __align__(16) char dynsmem[];

// ---------------- helpers --------------------------------------------------------
__device__ __forceinline__ float sigm(float x) { return 1.0f / (1.0f + expf(-x)); }

__device__ __forceinline__ void split_tf32(float x, float& hi, float& lo) {
    uint32_t h;
    asm("cvt.rna.tf32.f32 %0, %1;" : "=r"(h) : "f"(x));
    hi = __uint_as_float(h);
    float r = x - hi;
    uint32_t l;
    asm("cvt.rna.tf32.f32 %0, %1;" : "=r"(l) : "f"(r));
    lo = __uint_as_float(l);
}
__device__ __forceinline__ uint32_t smem_u32(const void* p) {
    uint32_t a;
    asm("{ .reg .u64 t; cvta.to.shared.u64 t, %1; cvt.u32.u64 %0, t; }"
        : "=r"(a) : "l"(p));
    return a;
}
__device__ __forceinline__ void cp16(uint32_t dst, const void* src) {
    asm volatile("cp.async.cg.shared.global [%0], [%1], 16;"
                 :: "r"(dst), "l"(src) : "memory");
}
__device__ __forceinline__ void cp_commit() {
    asm volatile("cp.async.commit_group;" ::: "memory");
}
__device__ __forceinline__ void cp_wait1() {
    asm volatile("cp.async.wait_group 1;" ::: "memory");
}
__device__ __forceinline__ void cp_wait0() {
    asm volatile("cp.async.wait_group 0;" ::: "memory");
}
__device__ __forceinline__ void mma_tf32(float* d, const uint32_t* a,
                                         uint32_t b0, uint32_t b1) {
    asm volatile(
        "mma.sync.aligned.m16n8k8.row.col.f32.tf32.tf32.f32 "
        "{%0,%1,%2,%3}, {%4,%5,%6,%7}, {%8,%9}, {%0,%1,%2,%3};"
        : "+f"(d[0]), "+f"(d[1]), "+f"(d[2]), "+f"(d[3])
        : "r"(a[0]), "r"(a[1]), "r"(a[2]), "r"(a[3]), "r"(b0), "r"(b1));
}

// ---------------- tf32 split kernels ---------------------------------------------
__global__ void split2_kernel(const float* __restrict__ in, float* __restrict__ oh,
                              float* __restrict__ ol, int n4) {
    int i = blockIdx.x * blockDim.x + threadIdx.x;
    if (i >= n4) return;
    float4 a = reinterpret_cast<const float4*>(in)[i];
    float4 h, l;
    split_tf32(a.x, h.x, l.x);
    split_tf32(a.y, h.y, l.y);
    split_tf32(a.z, h.z, l.z);
    split_tf32(a.w, h.w, l.w);
    reinterpret_cast<float4*>(oh)[i] = h;
    reinterpret_cast<float4*>(ol)[i] = l;
}

__global__ void embed_split_kernel(const int* __restrict__ sent,
                                   const float* __restrict__ emb,
                                   float* __restrict__ oh, float* __restrict__ ol) {
    int i = blockIdx.x * blockDim.x + threadIdx.x;
    int total = TT * BB * (EE / 4);
    if (i >= total) return;
    int tb = i >> 6, e4 = i & 63;
    int v = sent[tb];
    float4 a = reinterpret_cast<const float4*>(emb + (size_t)v * EE)[e4];
    float4 h, l;
    split_tf32(a.x, h.x, l.x);
    split_tf32(a.y, h.y, l.y);
    split_tf32(a.z, h.z, l.z);
    split_tf32(a.w, h.w, l.w);
    reinterpret_cast<float4*>(oh)[i] = h;
    reinterpret_cast<float4*>(ol)[i] = l;
}

// ---------------- 3xTF32 mma.sync GEMM (validated round 4) ----------------------
#define TPAD 20
#define TILE_F (128 * TPAD)
#define STAGE_F (4 * TILE_F)
#define GEMM_SMEM (2 * STAGE_F * 4)

__global__ __launch_bounds__(256) void tf32_gemm(
    const float* __restrict__ Ah, const float* __restrict__ Al,
    const float* __restrict__ Wh, const float* __restrict__ Wl,
    const float* __restrict__ bi1, const float* __restrict__ bi2,
    float* __restrict__ C, int K)
{
    float* smem = reinterpret_cast<float*>(dynsmem);
    const uint32_t sb = smem_u32(smem);
    const int tid = threadIdx.x, lane = tid & 31, wid = tid >> 5;
    const int wm = wid & 1, wn = wid >> 1;
    const int bn = blockIdx.x * 128, bm = blockIdx.y * 128;
    const int nch = K >> 4;
    const int qr = lane >> 2, qc = lane & 3;

    float acc[4][4][4];
    #pragma unroll
    for (int mi = 0; mi < 4; mi++)
        #pragma unroll
        for (int ni = 0; ni < 4; ni++)
            #pragma unroll
            for (int q = 0; q < 4; q++) acc[mi][ni][q] = 0.0f;

    auto issue = [&](int c, int st) {
        #pragma unroll
        for (int i = 0; i < 8; i++) {
            int s = tid + i * 256;
            int tile = s >> 9;
            int r = (s >> 2) & 127;
            int sub = s & 3;
            const float* g;
            if (tile == 0)      g = Ah + (size_t)(bm + r) * K + c * 16 + sub * 4;
            else if (tile == 1) g = Al + (size_t)(bm + r) * K + c * 16 + sub * 4;
            else if (tile == 2) g = Wh + (size_t)(bn + r) * K + c * 16 + sub * 4;
            else                g = Wl + (size_t)(bn + r) * K + c * 16 + sub * 4;
            uint32_t d = sb + (uint32_t)(st * STAGE_F + tile * TILE_F + r * TPAD + sub * 4) * 4;
            cp16(d, g);
        }
        cp_commit();
    };

    issue(0, 0);

    for (int c = 0; c < nch; c++) {
        const int st = c & 1;
        if (c + 1 < nch) { issue(c + 1, st ^ 1); cp_wait1(); }
        else cp_wait0();
        __syncthreads();

        const float* Ah_s = smem + st * STAGE_F;
        const float* Al_s = Ah_s + TILE_F;
        const float* Wh_s = Ah_s + 2 * TILE_F;
        const float* Wl_s = Ah_s + 3 * TILE_F;

        #pragma unroll
        for (int s8 = 0; s8 < 16; s8 += 8) {
            #pragma unroll
            for (int t = 0; t < 3; t++) {
                const float* At = (t == 2) ? Al_s : Ah_s;
                const float* Wt = (t == 1) ? Wl_s : Wh_s;
                uint32_t a[4][4];
                #pragma unroll
                for (int mi = 0; mi < 4; mi++) {
                    int m = wm * 64 + mi * 16 + qr;
                    const uint32_t* p =
                        reinterpret_cast<const uint32_t*>(At + m * TPAD + s8 + qc);
                    a[mi][0] = p[0];
                    a[mi][2] = p[4];
                    const uint32_t* p8 =
                        reinterpret_cast<const uint32_t*>(At + (m + 8) * TPAD + s8 + qc);
                    a[mi][1] = p8[0];
                    a[mi][3] = p8[4];
                }
                #pragma unroll
                for (int ni = 0; ni < 4; ni++) {
                    int n = wn * 32 + ni * 8 + qr;
                    const uint32_t* p =
                        reinterpret_cast<const uint32_t*>(Wt + n * TPAD + s8 + qc);
                    uint32_t b0 = p[0], b1 = p[4];
                    #pragma unroll
                    for (int mi = 0; mi < 4; mi++)
                        mma_tf32(acc[mi][ni], a[mi], b0, b1);
                }
            }
        }
        __syncthreads();
    }

    #pragma unroll
    for (int ni = 0; ni < 4; ni++) {
        int col = bn + wn * 32 + ni * 8 + 2 * qc;
        float2 s1 = *reinterpret_cast<const float2*>(bi1 + col);
        float2 s2 = *reinterpret_cast<const float2*>(bi2 + col);
        float bx = s1.x + s2.x, by = s1.y + s2.y;
        #pragma unroll
        for (int mi = 0; mi < 4; mi++) {
            int row = bm + wm * 64 + mi * 16 + qr;
            float2 v0 = make_float2(acc[mi][ni][0] + bx, acc[mi][ni][1] + by);
            float2 v1 = make_float2(acc[mi][ni][2] + bx, acc[mi][ni][3] + by);
            *reinterpret_cast<float2*>(&C[(size_t)row * G4H + col]) = v0;
            *reinterpret_cast<float2*>(&C[(size_t)(row + 8) * G4H + col]) = v1;
        }
    }
}

// ---------------- feats: 3xTF32 MMA, C(M,32) = H(M,1024) @ Wout(32,1024)^T + b --
#define FT_PAD 36
#define FT_AF (128 * FT_PAD)
#define FT_BF (32 * FT_PAD)
#define FT_STAGE (2 * (FT_AF + FT_BF))
#define FEATS_SMEM (2 * FT_STAGE * 4)      // 92160 B

__global__ __launch_bounds__(256) void feats_gemm(
    const float* __restrict__ Ah, const float* __restrict__ Al,
    const float* __restrict__ Wh, const float* __restrict__ Wl,
    const float* __restrict__ bo, float* __restrict__ C)
{
    float* smem = reinterpret_cast<float*>(dynsmem);
    const uint32_t sb = smem_u32(smem);
    const int tid = threadIdx.x, lane = tid & 31, wid = tid >> 5;
    const int bm = blockIdx.x * 128;
    const int qr = lane >> 2, qc = lane & 3;
    const int K = 2 * HH;                    // 1024
    const int nch = K >> 5;                  // 32 chunks of BK=32

    float acc[4][4];
    #pragma unroll
    for (int ni = 0; ni < 4; ni++)
        #pragma unroll
        for (int q = 0; q < 4; q++) acc[ni][q] = 0.0f;

    auto issue = [&](int c, int st) {
        #pragma unroll
        for (int i = 0; i < 10; i++) {
            int s = tid + i * 256;
            if (s >= 2560) break;
            const float* g;
            uint32_t off;
            if (s < 1024) {           // Ah: 128 rows x 8 segs
                int r = s >> 3, seg = s & 7;
                g = Ah + (size_t)(bm + r) * K + c * 32 + seg * 4;
                off = (uint32_t)(r * FT_PAD + seg * 4);
            } else if (s < 2048) {    // Al
                int s2 = s - 1024;
                int r = s2 >> 3, seg = s2 & 7;
                g = Al + (size_t)(bm + r) * K + c * 32 + seg * 4;
                off = (uint32_t)(FT_AF + r * FT_PAD + seg * 4);
            } else if (s < 2304) {    // Wh: 32 rows x 8 segs
                int s2 = s - 2048;
                int r = s2 >> 3, seg = s2 & 7;
                g = Wh + (size_t)r * K + c * 32 + seg * 4;
                off = (uint32_t)(2 * FT_AF + r * FT_PAD + seg * 4);
            } else {                  // Wl
                int s2 = s - 2304;
                int r = s2 >> 3, seg = s2 & 7;
                g = Wl + (size_t)r * K + c * 32 + seg * 4;
                off = (uint32_t)(2 * FT_AF + FT_BF + r * FT_PAD + seg * 4);
            }
            cp16(sb + (uint32_t)(st * FT_STAGE + off) * 4, g);
        }
        cp_commit();
    };

    issue(0, 0);
    for (int c = 0; c < nch; c++) {
        const int st = c & 1;
        if (c + 1 < nch) { issue(c + 1, st ^ 1); cp_wait1(); }
        else cp_wait0();
        __syncthreads();

        const float* Ah_s = smem + st * FT_STAGE;
        const float* Al_s = Ah_s + FT_AF;
        const float* Wh_s = Ah_s + 2 * FT_AF;
        const float* Wl_s = Wh_s + FT_BF;

        #pragma unroll
        for (int s8 = 0; s8 < 32; s8 += 8) {
            const int m = wid * 16 + qr;
            uint32_t ah[4], al[4];
            {
                const uint32_t* p  = reinterpret_cast<const uint32_t*>(Ah_s + m * FT_PAD + s8 + qc);
                const uint32_t* p8 = reinterpret_cast<const uint32_t*>(Ah_s + (m + 8) * FT_PAD + s8 + qc);
                ah[0] = p[0]; ah[1] = p8[0]; ah[2] = p[4]; ah[3] = p8[4];
                const uint32_t* q  = reinterpret_cast<const uint32_t*>(Al_s + m * FT_PAD + s8 + qc);
                const uint32_t* q8 = reinterpret_cast<const uint32_t*>(Al_s + (m + 8) * FT_PAD + s8 + qc);
                al[0] = q[0]; al[1] = q8[0]; al[2] = q[4]; al[3] = q8[4];
            }
            #pragma unroll
            for (int ni = 0; ni < 4; ni++) {
                int n = ni * 8 + qr;
                const uint32_t* p = reinterpret_cast<const uint32_t*>(Wh_s + n * FT_PAD + s8 + qc);
                const uint32_t* q = reinterpret_cast<const uint32_t*>(Wl_s + n * FT_PAD + s8 + qc);
                uint32_t bh0 = p[0], bh1 = p[4];
                uint32_t bl0 = q[0], bl1 = q[4];
                mma_tf32(acc[ni], ah, bh0, bh1);
                mma_tf32(acc[ni], ah, bl0, bl1);
                mma_tf32(acc[ni], al, bh0, bh1);
            }
        }
        __syncthreads();
    }

    #pragma unroll
    for (int ni = 0; ni < 4; ni++) {
        int col = ni * 8 + 2 * qc;
        float2 bb = *reinterpret_cast<const float2*>(bo + col);
        int row = bm + wid * 16 + qr;
        *reinterpret_cast<float2*>(&C[(size_t)row * KK + col]) =
            make_float2(acc[ni][0] + bb.x, acc[ni][1] + bb.y);
        *reinterpret_cast<float2*>(&C[(size_t)(row + 8) * KK + col]) =
            make_float2(acc[ni][2] + bb.x, acc[ni][3] + bb.y);
    }
}

// ---------------- persistent LSTM v4.1: wait-at-top barrier ----------------------
#define HR 516
#define PSD 68
#define OFF_PS (64 * HR * 4)
#define PS_W   (32 * PSD)
#define OFF_GS (OFF_PS + 8 * PS_W * 4)
#define LSTM4_SMEM (OFF_GS + 32 * PSD * 4)

__global__ __launch_bounds__(256, 1) void lstm_mma4_kernel(
    const float* __restrict__ xpf, const float* __restrict__ xpr,
    const float* __restrict__ whf, const float* __restrict__ whr,
    float* hst, float* __restrict__ hb_hi, float* __restrict__ hb_lo,
    unsigned* bar)
{
    float* Hs = reinterpret_cast<float*>(dynsmem);
    float* Ps = reinterpret_cast<float*>(dynsmem + OFF_PS);
    float* Gs = reinterpret_cast<float*>(dynsmem + OFF_GS);
    const uint32_t sb = smem_u32(dynsmem);
    const int tid = threadIdx.x, lane = tid & 31, wid = tid >> 5;
    const int dir = blockIdx.x >> 6, sub = blockIdx.x & 63, j0 = sub * 8;
    const float* W  = dir ? whr : whf;
    const float* xp = dir ? xpr : xpf;
    const int qr = lane >> 2, qc = lane & 3;
    const int k0 = wid * 64;

    // gather W_hh fragments (hi & lo) into registers — once per layer
    uint32_t Whi[2][8][4], Wlo[2][8][4];
    #pragma unroll
    for (int At = 0; At < 2; At++) {
        int mA = At * 16 + qr;
        int row0 = (mA >> 3) * 512 + j0 + (mA & 7);
        int mB = mA + 8;
        int row1 = (mB >> 3) * 512 + j0 + (mB & 7);
        #pragma unroll
        for (int ko = 0; ko < 8; ko++) {
            int kb = k0 + ko * 8 + qc;
            float v[4];
            v[0] = W[(size_t)row0 * HH + kb];
            v[1] = W[(size_t)row1 * HH + kb];
            v[2] = W[(size_t)row0 * HH + kb + 4];
            v[3] = W[(size_t)row1 * HH + kb + 4];
            #pragma unroll
            for (int r = 0; r < 4; r++) {
                float h_, l_;
                split_tf32(v[r], h_, l_);
                Whi[At][ko][r] = __float_as_uint(h_);
                Wlo[At][ko][r] = __float_as_uint(l_);
            }
        }
    }

    const int cb0 = tid >> 3,          cj0 = tid & 7;
    const int cb1 = (tid + 256) >> 3,  cj1 = tid & 7;
    float cc0 = 0.0f, cc1 = 0.0f;

    for (int s = 0; s < TT; s++) {
        const int rb = s & 1, wb = rb ^ 1;
        const int tt = dir ? (TT - 1 - s) : s;
        const float* xpt = xp + (size_t)tt * BB * G4H;
        const float* hsrc = hst + (size_t)(rb * 2 + dir) * (BB * HH);
        float* hdst = hst + (size_t)(wb * 2 + dir) * (BB * HH);

        // xg loads issued BEFORE the barrier wait (execute in its shadow)
        float xg0[4], xg1[4];
        #pragma unroll
        for (int g = 0; g < 4; g++) {
            xg0[g] = xpt[cb0 * G4H + g * HH + j0 + cj0];
            xg1[g] = xpt[cb1 * G4H + g * HH + j0 + cj1];
        }

        // wait for previous step's h (arrivals posted at end of step s-1)
        if (s > 0) {
            if (tid == 0) {
                unsigned target = 64u * (unsigned)s;
                unsigned v;
                do {
                    asm volatile("ld.acquire.gpu.global.u32 %0, [%1];"
                                 : "=r"(v) : "l"(bar + dir) : "memory");
                } while (v < target);
            }
            __syncthreads();
        }

        // per-warp cp.async of this warp's k-slice: 64 rows x 64 floats = 16KB
        #pragma unroll
        for (int i = 0; i < 32; i++) {
            int idx = lane + i * 32;
            int row = idx >> 4, seg = idx & 15;
            cp16(sb + (uint32_t)(row * HR + k0 + seg * 4) * 4,
                 hsrc + (size_t)row * HH + k0 + seg * 4);
        }
        cp_commit();
        cp_wait0();
        __syncwarp();

        float acc[2][8][4];
        #pragma unroll
        for (int At = 0; At < 2; At++)
            #pragma unroll
            for (int nt = 0; nt < 8; nt++)
                #pragma unroll
                for (int q = 0; q < 4; q++) acc[At][nt][q] = 0.0f;

        #pragma unroll
        for (int ko = 0; ko < 8; ko++) {
            #pragma unroll
            for (int nt = 0; nt < 8; nt++) {
                const float* p = Hs + (nt * 8 + qr) * HR + k0 + ko * 8 + qc;
                float b0v = p[0], b1v = p[4];
                float bh0f, bl0f, bh1f, bl1f;
                split_tf32(b0v, bh0f, bl0f);
                split_tf32(b1v, bh1f, bl1f);
                uint32_t bh0 = __float_as_uint(bh0f), bl0 = __float_as_uint(bl0f);
                uint32_t bh1 = __float_as_uint(bh1f), bl1 = __float_as_uint(bl1f);
                #pragma unroll
                for (int At = 0; At < 2; At++) {
                    mma_tf32(acc[At][nt], Whi[At][ko], bh0, bh1);
                    mma_tf32(acc[At][nt], Wlo[At][ko], bh0, bh1);
                    mma_tf32(acc[At][nt], Whi[At][ko], bl0, bl1);
                }
            }
        }

        float* Pw = Ps + wid * PS_W;
        #pragma unroll
        for (int At = 0; At < 2; At++)
            #pragma unroll
            for (int nt = 0; nt < 8; nt++) {
                int m = At * 16 + qr, n = nt * 8 + 2 * qc;
                *reinterpret_cast<float2*>(&Pw[m * PSD + n]) =
                    make_float2(acc[At][nt][0], acc[At][nt][1]);
                *reinterpret_cast<float2*>(&Pw[(m + 8) * PSD + n]) =
                    make_float2(acc[At][nt][2], acc[At][nt][3]);
            }
        __syncthreads();

        {
            int m = tid >> 3, n0 = (tid & 7) * 8;
            float4 s0 = make_float4(0.f, 0.f, 0.f, 0.f);
            float4 s1 = make_float4(0.f, 0.f, 0.f, 0.f);
            #pragma unroll
            for (int w = 0; w < 8; w++) {
                const float* q = Ps + w * PS_W + m * PSD + n0;
                float4 a = *reinterpret_cast<const float4*>(q);
                float4 b = *reinterpret_cast<const float4*>(q + 4);
                s0.x += a.x; s0.y += a.y; s0.z += a.z; s0.w += a.w;
                s1.x += b.x; s1.y += b.y; s1.z += b.z; s1.w += b.w;
            }
            *reinterpret_cast<float4*>(&Gs[m * PSD + n0]) = s0;
            *reinterpret_cast<float4*>(&Gs[m * PSD + n0 + 4]) = s1;
        }
        __syncthreads();

        {
            float gi = Gs[(0 * 8 + cj0) * PSD + cb0] + xg0[0];
            float gf = Gs[(1 * 8 + cj0) * PSD + cb0] + xg0[1];
            float gg = Gs[(2 * 8 + cj0) * PSD + cb0] + xg0[2];
            float go = Gs[(3 * 8 + cj0) * PSD + cb0] + xg0[3];
            cc0 = sigm(gf) * cc0 + sigm(gi) * tanhf(gg);
            float hv = sigm(go) * tanhf(cc0);
            hdst[(size_t)cb0 * HH + j0 + cj0] = hv;
            float hh_, hl_;
            split_tf32(hv, hh_, hl_);
            size_t o = (size_t)(tt * BB + cb0) * (2 * HH) + (size_t)dir * HH + j0 + cj0;
            hb_hi[o] = hh_; hb_lo[o] = hl_;
        }
        {
            float gi = Gs[(0 * 8 + cj1) * PSD + cb1] + xg1[0];
            float gf = Gs[(1 * 8 + cj1) * PSD + cb1] + xg1[1];
            float gg = Gs[(2 * 8 + cj1) * PSD + cb1] + xg1[2];
            float go = Gs[(3 * 8 + cj1) * PSD + cb1] + xg1[3];
            cc1 = sigm(gf) * cc1 + sigm(gi) * tanhf(gg);
            float hv = sigm(go) * tanhf(cc1);
            hdst[(size_t)cb1 * HH + j0 + cj1] = hv;
            float hh_, hl_;
            split_tf32(hv, hh_, hl_);
            size_t o = (size_t)(tt * BB + cb1) * (2 * HH) + (size_t)dir * HH + j0 + cj1;
            hb_hi[o] = hh_; hb_lo[o] = hl_;
        }

        // arrive: make h visible, post arrival; waiting happens at top of next step
        if (s + 1 < TT) {
            __threadfence();
            __syncthreads();
            if (tid == 0) atomicAdd(&bar[dir], 1u);
        }
    }
}

// ---------------- Viterbi --------------------------------------------------------
__global__ __launch_bounds__(32) void viterbi_kernel(
    const float* __restrict__ feats, const float* __restrict__ trans,
    const float* __restrict__ startt, const float* __restrict__ stopt,
    float* __restrict__ out, int out_size)
{
    int b = blockIdx.x;
    int j = threadIdx.x;
    __shared__ unsigned char bp[TT - 1][KK];
    __shared__ int path[TT];

    float tr[KK];
    #pragma unroll
    for (int k = 0; k < KK; k++) tr[k] = trans[j * KK + k];

    float dp = startt[j] + feats[(size_t)b * KK + j];
    for (int t = 1; t < TT; t++) {
        float best = -INFINITY;
        int arg = 0;
        #pragma unroll
        for (int k = 0; k < KK; k++) {
            float v = tr[k] + __shfl_sync(0xffffffffu, dp, k);
            if (v > best) { best = v; arg = k; }
        }
        bp[t - 1][j] = (unsigned char)arg;
        dp = best + feats[((size_t)t * BB + b) * KK + j];
    }
    dp += stopt[j];

    float bv = dp; int bi = j;
    #pragma unroll
    for (int off = 16; off; off >>= 1) {
        float ov = __shfl_down_sync(0xffffffffu, bv, off);
        int   oi = __shfl_down_sync(0xffffffffu, bi, off);
        if (ov > bv || (ov == bv && oi < bi)) { bv = ov; bi = oi; }
    }
    bv = __shfl_sync(0xffffffffu, bv, 0);
    bi = __shfl_sync(0xffffffffu, bi, 0);

    if (j == 0) {
        path[TT - 1] = bi;
        int tag = bi;
        for (int t = TT - 2; t >= 0; t--) {
            tag = bp[t][tag];
            path[t] = tag;
        }
    }
    __syncwarp();

    int pathsOff = out_size - TT * BB;
    if (pathsOff >= (int)BB) {
        if (j == 0) out[b] = bv;
    } else if (pathsOff < 0) {
        if (j == 0 && b < out_size) out[b] = bv;
        return;
    }
    for (int t = j; t < TT; t += 32)
        out[pathsOff + t * BB + b] = (float)path[t];
}

// ---------------- launch ---------------------------------------------------------
extern "C" void kernel_launch(void* const* d_in, const int* in_sizes, int n_in,
                              void* d_out, int out_size) {
    const int*   sent    = (const int*)d_in[0];
    const float* emb     = (const float*)d_in[1];
    const float* wih_l0f = (const float*)d_in[2];
    const float* whh_l0f = (const float*)d_in[3];
    const float* bih_l0f = (const float*)d_in[4];
    const float* bhh_l0f = (const float*)d_in[5];
    const float* wih_l0r = (const float*)d_in[6];
    const float* whh_l0r = (const float*)d_in[7];
    const float* bih_l0r = (const float*)d_in[8];
    const float* bhh_l0r = (const float*)d_in[9];
    const float* wih_l1f = (const float*)d_in[10];
    const float* whh_l1f = (const float*)d_in[11];
    const float* bih_l1f = (const float*)d_in[12];
    const float* bhh_l1f = (const float*)d_in[13];
    const float* wih_l1r = (const float*)d_in[14];
    const float* whh_l1r = (const float*)d_in[15];
    const float* bih_l1r = (const float*)d_in[16];
    const float* bhh_l1r = (const float*)d_in[17];
    const float* W_out   = (const float*)d_in[18];
    const float* b_out   = (const float*)d_in[19];
    const float* transit = (const float*)d_in[20];
    const float* start_t = (const float*)d_in[21];
    const float* stop_t  = (const float*)d_in[22];

    float *xpf, *xpr, *feats, *hst;
    unsigned* bar;
    cudaGetSymbolAddress((void**)&xpf,   g_xpf);
    cudaGetSymbolAddress((void**)&xpr,   g_xpr);
    cudaGetSymbolAddress((void**)&feats, g_feats);
    cudaGetSymbolAddress((void**)&hst,   g_hst);
    cudaGetSymbolAddress((void**)&bar,   g_bar);
    float *as, *hsx, *w0f, *w0r, *w1f, *w1r, *wo;
    cudaGetSymbolAddress((void**)&as,  g_as);
    cudaGetSymbolAddress((void**)&hsx, g_hs);
    cudaGetSymbolAddress((void**)&w0f, g_w0f);
    cudaGetSymbolAddress((void**)&w0r, g_w0r);
    cudaGetSymbolAddress((void**)&w1f, g_w1f);
    cudaGetSymbolAddress((void**)&w1r, g_w1r);
    cudaGetSymbolAddress((void**)&wo,  g_wo);
    const size_t ASZ = (size_t)MROWS*EE, HSZ = (size_t)MROWS*2*HH;
    const size_t W0SZ = (size_t)G4H*EE,  W1SZ = (size_t)G4H*2*HH;
    const size_t WOSZ = (size_t)KK*2*HH;

    cudaFuncSetAttribute(tf32_gemm,
                         cudaFuncAttributeMaxDynamicSharedMemorySize, GEMM_SMEM);
    cudaFuncSetAttribute(feats_gemm,
                         cudaFuncAttributeMaxDynamicSharedMemorySize, FEATS_SMEM);
    cudaFuncSetAttribute(lstm_mma4_kernel,
                         cudaFuncAttributeMaxDynamicSharedMemorySize, LSTM4_SMEM);

    // 1) embedding (fused gather + tf32 split)
    embed_split_kernel<<<(TT * BB * (EE / 4) + 255) / 256, 256>>>(
        sent, emb, as, as + ASZ);

    // 2) split weights (input projections + W_out)
    split2_kernel<<<(int)(W0SZ/4 + 255)/256, 256>>>(wih_l0f, w0f, w0f + W0SZ, (int)(W0SZ/4));
    split2_kernel<<<(int)(W0SZ/4 + 255)/256, 256>>>(wih_l0r, w0r, w0r + W0SZ, (int)(W0SZ/4));
    split2_kernel<<<(int)(W1SZ/4 + 255)/256, 256>>>(wih_l1f, w1f, w1f + W1SZ, (int)(W1SZ/4));
    split2_kernel<<<(int)(W1SZ/4 + 255)/256, 256>>>(wih_l1r, w1r, w1r + W1SZ, (int)(W1SZ/4));
    split2_kernel<<<(int)(WOSZ/4 + 255)/256, 256>>>(W_out, wo, wo + WOSZ, (int)(WOSZ/4));

    dim3 gg(G4H / 128, MROWS / 128);

    // 3) layer-0 input projections
    tf32_gemm<<<gg, 256, GEMM_SMEM>>>(as, as + ASZ, w0f, w0f + W0SZ,
                                      bih_l0f, bhh_l0f, xpf, EE);
    tf32_gemm<<<gg, 256, GEMM_SMEM>>>(as, as + ASZ, w0r, w0r + W0SZ,
                                      bih_l0r, bhh_l0r, xpr, EE);

    // 4) layer-0 recurrence; writes h splits into hsx
    cudaMemsetAsync(hst, 0, sizeof(float) * 2 * 2 * BB * HH);
    cudaMemsetAsync(bar, 0, sizeof(unsigned) * 2);
    lstm_mma4_kernel<<<128, 256, LSTM4_SMEM>>>(xpf, xpr, whh_l0f, whh_l0r,
                                               hst, hsx, hsx + HSZ, bar);

    // 5) layer-1 input projections (K = 2H), consume hsx
    tf32_gemm<<<gg, 256, GEMM_SMEM>>>(hsx, hsx + HSZ, w1f, w1f + W1SZ,
                                      bih_l1f, bhh_l1f, xpf, 2 * HH);
    tf32_gemm<<<gg, 256, GEMM_SMEM>>>(hsx, hsx + HSZ, w1r, w1r + W1SZ,
                                      bih_l1r, bhh_l1r, xpr, 2 * HH);

    // 6) layer-1 recurrence; overwrites hsx with layer-1 output splits
    cudaMemsetAsync(hst, 0, sizeof(float) * 2 * 2 * BB * HH);
    cudaMemsetAsync(bar, 0, sizeof(unsigned) * 2);
    lstm_mma4_kernel<<<128, 256, LSTM4_SMEM>>>(xpf, xpr, whh_l1f, whh_l1r,
                                               hst, hsx, hsx + HSZ, bar);

    // 7) emissions via 3xTF32 MMA
    feats_gemm<<<MROWS / 128, 256, FEATS_SMEM>>>(hsx, hsx + HSZ, wo, wo + WOSZ,
                                                 b_out, feats);

    // 8) Viterbi decode + output write
    viterbi_kernel<<<BB, 32>>>(feats, transit, start_t, stop_t, (float*)d_out, out_size);
}